// round 1
// baseline (speedup 1.0000x reference)
#include <cuda_runtime.h>
#include <math.h>

// Problem constants
#define SEQ 4096
#define DIM 1024
#define NH  16
#define HD2 64   // head dim

// Scratch (no allocations allowed)
__device__ float g_q[NH * SEQ * HD2];     // [h][s][hd]
__device__ float g_k[NH * SEQ * HD2];
__device__ float g_v[NH * SEQ * HD2];
__device__ float g_att[SEQ * DIM];        // [s][d]

// ---------------------------------------------------------------------------
// GEMM: C[M=4096, N=1024] = A[M,K=1024] * W[N,K]^T
// mode 0: out[m*1024+n] = c                        (output projection)
// mode 1: RoPE epilogue + scatter to [h][s][hd]    (Q, K)
// mode 2: scatter to [h][s][hd]                    (V)
// 128x128 tile, BK=8, 256 threads, 8x8 per thread.
// ---------------------------------------------------------------------------
__global__ void __launch_bounds__(256) gemm_kernel(
    const float* __restrict__ A, const float* __restrict__ W,
    float* __restrict__ out,
    const float* __restrict__ cosT, const float* __restrict__ sinT,
    int mode)
{
    __shared__ float As[8][128];
    __shared__ float Bs[8][128];

    const int tid = threadIdx.x;
    const int tx = tid & 15;        // 0..15 -> 8 cols each
    const int ty = tid >> 4;        // 0..15 -> 8 rows each
    const int mBase = blockIdx.y * 128;
    const int nBase = blockIdx.x * 128;

    const int lr = tid >> 1;        // 0..127 row within tile
    const int lk = (tid & 1) << 2;  // 0 or 4

    const float* Ap = A + (size_t)(mBase + lr) * DIM + lk;
    const float* Wp = W + (size_t)(nBase + lr) * DIM + lk;

    float acc[8][8];
#pragma unroll
    for (int i = 0; i < 8; i++)
#pragma unroll
        for (int j = 0; j < 8; j++) acc[i][j] = 0.f;

    for (int k0 = 0; k0 < DIM; k0 += 8) {
        float4 av = *(const float4*)(Ap + k0);
        float4 bv = *(const float4*)(Wp + k0);
        __syncthreads();
        As[lk + 0][lr] = av.x; As[lk + 1][lr] = av.y;
        As[lk + 2][lr] = av.z; As[lk + 3][lr] = av.w;
        Bs[lk + 0][lr] = bv.x; Bs[lk + 1][lr] = bv.y;
        Bs[lk + 2][lr] = bv.z; Bs[lk + 3][lr] = bv.w;
        __syncthreads();
#pragma unroll
        for (int kk = 0; kk < 8; kk++) {
            float a[8], b[8];
            *(float4*)(a)     = *(const float4*)(&As[kk][ty * 8]);
            *(float4*)(a + 4) = *(const float4*)(&As[kk][ty * 8 + 4]);
            *(float4*)(b)     = *(const float4*)(&Bs[kk][tx * 8]);
            *(float4*)(b + 4) = *(const float4*)(&Bs[kk][tx * 8 + 4]);
#pragma unroll
            for (int i = 0; i < 8; i++)
#pragma unroll
                for (int j = 0; j < 8; j++)
                    acc[i][j] += a[i] * b[j];
        }
    }

    // Epilogue
#pragma unroll
    for (int i = 0; i < 8; i++) {
        const int m = mBase + ty * 8 + i;
        if (mode == 0) {
            float* dst = out + (size_t)m * DIM + nBase + tx * 8;
            *(float4*)(dst)     = make_float4(acc[i][0], acc[i][1], acc[i][2], acc[i][3]);
            *(float4*)(dst + 4) = make_float4(acc[i][4], acc[i][5], acc[i][6], acc[i][7]);
        } else {
#pragma unroll
            for (int j = 0; j < 8; j += 2) {
                const int n = nBase + tx * 8 + j;    // even, pairs stay intra-thread
                const int head = n >> 6;
                const int hd = n & 63;               // even
                float e = acc[i][j], o = acc[i][j + 1];
                float re = e, ro = o;
                if (mode == 1) {
                    const int f = hd >> 1;           // 0..31
                    const float c  = cosT[m * (HD2 / 2) + f];
                    const float sn = sinT[m * (HD2 / 2) + f];
                    re = e * c - o * sn;
                    ro = e * sn + o * c;
                }
                float* dst = out + ((size_t)head * SEQ + m) * HD2 + hd;
                dst[0] = re;
                dst[1] = ro;
            }
        }
    }
}

// ---------------------------------------------------------------------------
// Flash attention: one CTA per (64-query tile, head). Online softmax.
// 64-key inner tiles, HD=64, fp32, causal (analytic mask).
// Dynamic smem layout:
//   sQ[64][68]  Q transposed: sQ[d*68 + row]
//   sK[64][68]  K transposed: sK[d*68 + col]
//   sV[64][64]  V natural:    sV[col*64 + d]
//   sP[64][64]  probs:        sP[row*64 + col]
//   sM[64], sL[64], sC[64]
// ---------------------------------------------------------------------------
#define FLASH_SMEM ((64 * 68 * 2 + 64 * 64 * 2 + 64 * 3) * (int)sizeof(float))

__global__ void __launch_bounds__(256) flash_kernel(
    const float* __restrict__ Q, const float* __restrict__ K,
    const float* __restrict__ V, float* __restrict__ att)
{
    extern __shared__ float sm[];
    float* sQ = sm;                    // 64*68
    float* sK = sQ + 64 * 68;          // 64*68
    float* sV = sK + 64 * 68;          // 64*64
    float* sP = sV + 64 * 64;          // 64*64
    float* sM = sP + 64 * 64;          // 64
    float* sL = sM + 64;               // 64
    float* sC = sL + 64;               // 64

    const int tid = threadIdx.x;
    const int tx = tid & 15;
    const int ty = tid >> 4;
    const int qblk = blockIdx.x;
    const int head = blockIdx.y;

    const float* Qh = Q + ((size_t)head * SEQ + qblk * 64) * HD2;

    // Load Q tile transposed
    for (int i = tid; i < 64 * 16; i += 256) {
        const int r  = i >> 4;
        const int d4 = (i & 15) << 2;
        float4 v = *(const float4*)(Qh + r * HD2 + d4);
        sQ[(d4 + 0) * 68 + r] = v.x;
        sQ[(d4 + 1) * 68 + r] = v.y;
        sQ[(d4 + 2) * 68 + r] = v.z;
        sQ[(d4 + 3) * 68 + r] = v.w;
    }
    if (tid < 64) { sM[tid] = -INFINITY; sL[tid] = 0.f; }

    float o[4][4];
#pragma unroll
    for (int i = 0; i < 4; i++)
#pragma unroll
        for (int j = 0; j < 4; j++) o[i][j] = 0.f;

    __syncthreads();

    for (int kb = 0; kb <= qblk; kb++) {
        const float* Kh = K + ((size_t)head * SEQ + kb * 64) * HD2;
        const float* Vh = V + ((size_t)head * SEQ + kb * 64) * HD2;

        // Load K (transposed) and V (natural)
        for (int i = tid; i < 64 * 16; i += 256) {
            const int r  = i >> 4;
            const int d4 = (i & 15) << 2;
            float4 kv = *(const float4*)(Kh + r * HD2 + d4);
            sK[(d4 + 0) * 68 + r] = kv.x;
            sK[(d4 + 1) * 68 + r] = kv.y;
            sK[(d4 + 2) * 68 + r] = kv.z;
            sK[(d4 + 3) * 68 + r] = kv.w;
            float4 vv = *(const float4*)(Vh + r * HD2 + d4);
            *(float4*)(sV + r * 64 + d4) = vv;
        }
        __syncthreads();

        // S = Q K^T  (4x4 per thread)
        float sa[4][4];
#pragma unroll
        for (int i = 0; i < 4; i++)
#pragma unroll
            for (int j = 0; j < 4; j++) sa[i][j] = 0.f;

#pragma unroll
        for (int d = 0; d < 64; d++) {
            float a[4], b[4];
            *(float4*)a = *(const float4*)(sQ + d * 68 + ty * 4);
            *(float4*)b = *(const float4*)(sK + d * 68 + tx * 4);
#pragma unroll
            for (int i = 0; i < 4; i++)
#pragma unroll
                for (int j = 0; j < 4; j++)
                    sa[i][j] += a[i] * b[j];
        }

        // scale + causal mask + write to sP
        const float scale = 0.125f;  // 1/sqrt(64)
#pragma unroll
        for (int i = 0; i < 4; i++) {
            const int qi = qblk * 64 + ty * 4 + i;
            float vals[4];
#pragma unroll
            for (int j = 0; j < 4; j++) {
                const int kj = kb * 64 + tx * 4 + j;
                vals[j] = (kj <= qi) ? sa[i][j] * scale : -INFINITY;
            }
            *(float4*)(sP + (ty * 4 + i) * 64 + tx * 4) =
                make_float4(vals[0], vals[1], vals[2], vals[3]);
        }
        __syncthreads();

        // Online softmax per row (threads 0..63)
        if (tid < 64) {
            const int r = tid;
            float* row = sP + r * 64;
            float m_old = sM[r];
            float m_new = m_old;
#pragma unroll 8
            for (int j = 0; j < 64; j++) m_new = fmaxf(m_new, row[j]);
            const float corr = expf(m_old - m_new);
            float lsum = 0.f;
#pragma unroll 8
            for (int j = 0; j < 64; j++) {
                const float p = expf(row[j] - m_new);
                row[j] = p;
                lsum += p;
            }
            sM[r] = m_new;
            sL[r] = sL[r] * corr + lsum;
            sC[r] = corr;
        }
        __syncthreads();

        // O = O*corr + P V
        float ci[4];
#pragma unroll
        for (int i = 0; i < 4; i++) ci[i] = sC[ty * 4 + i];
#pragma unroll
        for (int i = 0; i < 4; i++)
#pragma unroll
            for (int j = 0; j < 4; j++) o[i][j] *= ci[i];

#pragma unroll 4
        for (int col = 0; col < 64; col++) {
            float p0 = sP[(ty * 4 + 0) * 64 + col];
            float p1 = sP[(ty * 4 + 1) * 64 + col];
            float p2 = sP[(ty * 4 + 2) * 64 + col];
            float p3 = sP[(ty * 4 + 3) * 64 + col];
            float4 vv = *(const float4*)(sV + col * 64 + tx * 4);
            o[0][0] += p0 * vv.x; o[0][1] += p0 * vv.y; o[0][2] += p0 * vv.z; o[0][3] += p0 * vv.w;
            o[1][0] += p1 * vv.x; o[1][1] += p1 * vv.y; o[1][2] += p1 * vv.z; o[1][3] += p1 * vv.w;
            o[2][0] += p2 * vv.x; o[2][1] += p2 * vv.y; o[2][2] += p2 * vv.z; o[2][3] += p2 * vv.w;
            o[3][0] += p3 * vv.x; o[3][1] += p3 * vv.y; o[3][2] += p3 * vv.z; o[3][3] += p3 * vv.w;
        }
        __syncthreads();
    }

    // Final normalize + store to [s][d] layout
#pragma unroll
    for (int i = 0; i < 4; i++) {
        const int r = ty * 4 + i;
        const float inv = 1.f / sL[r];
        const int srow = qblk * 64 + r;
        float* dst = att + (size_t)srow * DIM + head * HD2 + tx * 4;
        *(float4*)dst = make_float4(o[i][0] * inv, o[i][1] * inv,
                                    o[i][2] * inv, o[i][3] * inv);
    }
}

// ---------------------------------------------------------------------------
// Launch
// Inputs: 0=x (1,4096,1024) f32, 1=cos (4096,32), 2=sin (4096,32),
//         3=mask (4096,4096) [ignored: causal analytic], 4=wq, 5=wk, 6=wv,
//         7=wo (1024,1024), 8=start_pos (=0)
// Output: (1,4096,1024) f32
// ---------------------------------------------------------------------------
extern "C" void kernel_launch(void* const* d_in, const int* in_sizes, int n_in,
                              void* d_out, int out_size)
{
    const float* x    = (const float*)d_in[0];
    const float* cosT = (const float*)d_in[1];
    const float* sinT = (const float*)d_in[2];
    const float* wq   = (const float*)d_in[4];
    const float* wk   = (const float*)d_in[5];
    const float* wv   = (const float*)d_in[6];
    const float* wo   = (const float*)d_in[7];
    float* out = (float*)d_out;

    float *qp, *kp, *vp, *ap;
    cudaGetSymbolAddress((void**)&qp, g_q);
    cudaGetSymbolAddress((void**)&kp, g_k);
    cudaGetSymbolAddress((void**)&vp, g_v);
    cudaGetSymbolAddress((void**)&ap, g_att);

    cudaFuncSetAttribute(flash_kernel,
                         cudaFuncAttributeMaxDynamicSharedMemorySize, FLASH_SMEM);

    dim3 ggrid(DIM / 128, SEQ / 128);
    gemm_kernel<<<ggrid, 256>>>(x, wq, qp, cosT, sinT, 1);
    gemm_kernel<<<ggrid, 256>>>(x, wk, kp, cosT, sinT, 1);
    gemm_kernel<<<ggrid, 256>>>(x, wv, vp, cosT, sinT, 2);

    dim3 fgrid(SEQ / 64, NH);
    flash_kernel<<<fgrid, 256, FLASH_SMEM>>>(qp, kp, vp, ap);

    gemm_kernel<<<ggrid, 256>>>(ap, wo, out, cosT, sinT, 0);
}

// round 2
// speedup vs baseline: 2.7276x; 2.7276x over previous
#include <cuda_runtime.h>
#include <math.h>
#include <stdint.h>

#define SEQ 4096
#define DIM 1024
#define NH  16
#define HDIM 64

// Scratch
__device__ float g_q[NH * SEQ * HDIM];   // [h][s][hd]
__device__ float g_k[NH * SEQ * HDIM];
__device__ float g_v[NH * SEQ * HDIM];
__device__ float g_att[SEQ * DIM];       // [s][d]

__device__ __forceinline__ uint32_t f2t(float f) {
    uint32_t u;
    asm("cvt.rna.tf32.f32 %0, %1;" : "=r"(u) : "f"(f));
    return u;
}

__device__ __forceinline__ void mma8(float c[4],
    uint32_t a0, uint32_t a1, uint32_t a2, uint32_t a3,
    uint32_t b0, uint32_t b1)
{
    asm volatile(
        "mma.sync.aligned.m16n8k8.row.col.f32.tf32.tf32.f32 "
        "{%0,%1,%2,%3},{%4,%5,%6,%7},{%8,%9},{%0,%1,%2,%3};"
        : "+f"(c[0]), "+f"(c[1]), "+f"(c[2]), "+f"(c[3])
        : "r"(a0), "r"(a1), "r"(a2), "r"(a3), "r"(b0), "r"(b1));
}

// ---------------------------------------------------------------------------
// TF32 GEMM: C[4096,1024] = A[M,K] * W[N,K]^T
// mode 0: plain row-major out; mode 1: RoPE + [h][s][hd]; mode 2: [h][s][hd]
// 128x128 tile, BK=16, 8 warps (4x2), warp tile 32x64, m16n8k8.
// ---------------------------------------------------------------------------
#define BK  16
#define SAS 20   // padded smem stride (floats)

__global__ void __launch_bounds__(256) gemm_tf32(
    const float* __restrict__ A, const float* __restrict__ W,
    float* __restrict__ out,
    const float* __restrict__ cosT, const float* __restrict__ sinT,
    int mode)
{
    __shared__ uint32_t sA[2][128 * SAS];
    __shared__ uint32_t sB[2][128 * SAS];

    const int tid  = threadIdx.x;
    const int lane = tid & 31;
    const int wid  = tid >> 5;
    const int wm   = wid >> 1;      // 0..3 (M)
    const int wn   = wid & 1;       // 0..1 (N)
    const int g4   = lane >> 2;     // group id 0..7
    const int t4   = lane & 3;      // thread-in-group

    const int mBase = blockIdx.y * 128;
    const int nBase = blockIdx.x * 128;

    const int lr = tid >> 2;         // 0..63 load row
    const int lk = (tid & 3) << 2;   // 0,4,8,12

    const float* Ag = A + (size_t)(mBase + lr) * DIM + lk;
    const float* Wg = W + (size_t)(nBase + lr) * DIM + lk;

    float c[2][8][4];
#pragma unroll
    for (int mt = 0; mt < 2; mt++)
#pragma unroll
        for (int nt = 0; nt < 8; nt++)
#pragma unroll
            for (int i = 0; i < 4; i++) c[mt][nt][i] = 0.f;

    float4 pa0, pa1, pb0, pb1;
    pa0 = *(const float4*)(Ag);
    pa1 = *(const float4*)(Ag + (size_t)64 * DIM);
    pb0 = *(const float4*)(Wg);
    pb1 = *(const float4*)(Wg + (size_t)64 * DIM);

    // store chunk 0 into buf 0
    {
        uint32_t* a = sA[0]; uint32_t* b = sB[0];
        a[lr * SAS + lk + 0] = f2t(pa0.x); a[lr * SAS + lk + 1] = f2t(pa0.y);
        a[lr * SAS + lk + 2] = f2t(pa0.z); a[lr * SAS + lk + 3] = f2t(pa0.w);
        a[(lr + 64) * SAS + lk + 0] = f2t(pa1.x); a[(lr + 64) * SAS + lk + 1] = f2t(pa1.y);
        a[(lr + 64) * SAS + lk + 2] = f2t(pa1.z); a[(lr + 64) * SAS + lk + 3] = f2t(pa1.w);
        b[lr * SAS + lk + 0] = f2t(pb0.x); b[lr * SAS + lk + 1] = f2t(pb0.y);
        b[lr * SAS + lk + 2] = f2t(pb0.z); b[lr * SAS + lk + 3] = f2t(pb0.w);
        b[(lr + 64) * SAS + lk + 0] = f2t(pb1.x); b[(lr + 64) * SAS + lk + 1] = f2t(pb1.y);
        b[(lr + 64) * SAS + lk + 2] = f2t(pb1.z); b[(lr + 64) * SAS + lk + 3] = f2t(pb1.w);
    }
    __syncthreads();

    const int NCHUNK = DIM / BK;   // 64
    for (int ch = 0; ch < NCHUNK; ch++) {
        const int cur = ch & 1;
        if (ch + 1 < NCHUNK) {
            const int off = (ch + 1) * BK;
            pa0 = *(const float4*)(Ag + off);
            pa1 = *(const float4*)(Ag + (size_t)64 * DIM + off);
            pb0 = *(const float4*)(Wg + off);
            pb1 = *(const float4*)(Wg + (size_t)64 * DIM + off);
        }

        const uint32_t* a_s = sA[cur];
        const uint32_t* b_s = sB[cur];
#pragma unroll
        for (int ks = 0; ks < 2; ks++) {
            const int kk = ks * 8 + t4;
            uint32_t af[2][4], bf[8][2];
#pragma unroll
            for (int mt = 0; mt < 2; mt++) {
                const int r = wm * 32 + mt * 16 + g4;
                af[mt][0] = a_s[r * SAS + kk];
                af[mt][1] = a_s[(r + 8) * SAS + kk];
                af[mt][2] = a_s[r * SAS + kk + 4];
                af[mt][3] = a_s[(r + 8) * SAS + kk + 4];
            }
#pragma unroll
            for (int nt = 0; nt < 8; nt++) {
                const int r = wn * 64 + nt * 8 + g4;
                bf[nt][0] = b_s[r * SAS + kk];
                bf[nt][1] = b_s[r * SAS + kk + 4];
            }
#pragma unroll
            for (int mt = 0; mt < 2; mt++)
#pragma unroll
                for (int nt = 0; nt < 8; nt++)
                    mma8(c[mt][nt], af[mt][0], af[mt][1], af[mt][2], af[mt][3],
                         bf[nt][0], bf[nt][1]);
        }

        if (ch + 1 < NCHUNK) {
            const int nb = cur ^ 1;
            uint32_t* a = sA[nb]; uint32_t* b = sB[nb];
            a[lr * SAS + lk + 0] = f2t(pa0.x); a[lr * SAS + lk + 1] = f2t(pa0.y);
            a[lr * SAS + lk + 2] = f2t(pa0.z); a[lr * SAS + lk + 3] = f2t(pa0.w);
            a[(lr + 64) * SAS + lk + 0] = f2t(pa1.x); a[(lr + 64) * SAS + lk + 1] = f2t(pa1.y);
            a[(lr + 64) * SAS + lk + 2] = f2t(pa1.z); a[(lr + 64) * SAS + lk + 3] = f2t(pa1.w);
            b[lr * SAS + lk + 0] = f2t(pb0.x); b[lr * SAS + lk + 1] = f2t(pb0.y);
            b[lr * SAS + lk + 2] = f2t(pb0.z); b[lr * SAS + lk + 3] = f2t(pb0.w);
            b[(lr + 64) * SAS + lk + 0] = f2t(pb1.x); b[(lr + 64) * SAS + lk + 1] = f2t(pb1.y);
            b[(lr + 64) * SAS + lk + 2] = f2t(pb1.z); b[(lr + 64) * SAS + lk + 3] = f2t(pb1.w);
            __syncthreads();
        }
    }

    // Epilogue
#pragma unroll
    for (int mt = 0; mt < 2; mt++) {
        const int r0 = mBase + wm * 32 + mt * 16 + g4;   // rows r0 and r0+8
#pragma unroll
        for (int nt = 0; nt < 8; nt++) {
            const int colg = nBase + wn * 64 + nt * 8 + (t4 << 1);  // even
            const float* cc = c[mt][nt];
            if (mode == 0) {
                *(float2*)(out + (size_t)r0 * DIM + colg)       = make_float2(cc[0], cc[1]);
                *(float2*)(out + (size_t)(r0 + 8) * DIM + colg) = make_float2(cc[2], cc[3]);
            } else {
                const int head = colg >> 6;
                const int hd   = colg & 63;       // even
                const int f    = hd >> 1;
#pragma unroll
                for (int h = 0; h < 2; h++) {
                    const int row = r0 + h * 8;
                    float e = cc[h * 2 + 0], o = cc[h * 2 + 1];
                    float re = e, ro = o;
                    if (mode == 1) {
                        const float cth = cosT[row * 32 + f];
                        const float sth = sinT[row * 32 + f];
                        re = e * cth - o * sth;
                        ro = e * sth + o * cth;
                    }
                    float* dst = out + ((size_t)head * SEQ + row) * HDIM + hd;
                    dst[0] = re; dst[1] = ro;
                }
            }
        }
    }
}

// ---------------------------------------------------------------------------
// TF32 flash attention: one CTA per (64-query tile, head).
// 8 warps (4x2 over the 64x64 tile, warp tile 16x32), m16n8k8 MMAs for
// S = Q K^T and O += P V. Online softmax, 4 threads/row with shuffles.
// ---------------------------------------------------------------------------
#define FP 68
#define FLASH_SMEM ((4 * 64 * FP + 3 * 64) * (int)sizeof(uint32_t))

__global__ void __launch_bounds__(256) flash_tf32(
    const float* __restrict__ Q, const float* __restrict__ K,
    const float* __restrict__ V, float* __restrict__ att)
{
    extern __shared__ uint32_t fsm[];
    uint32_t* sQ = fsm;               // [q][d]   tf32
    uint32_t* sK = sQ + 64 * FP;      // [k][d]   tf32
    uint32_t* sV = sK + 64 * FP;      // [d][key] tf32 (transposed)
    uint32_t* sP = sV + 64 * FP;      // scores f32, then probs tf32
    float* sPf = (float*)sP;
    float* sM = (float*)(sP + 64 * FP);
    float* sL = sM + 64;
    float* sC = sL + 64;

    const int tid  = threadIdx.x;
    const int lane = tid & 31;
    const int wid  = tid >> 5;
    const int wm   = wid >> 1;   // 0..3
    const int wn   = wid & 1;    // 0..1
    const int g4   = lane >> 2;
    const int t4   = lane & 3;

    const int qblk = gridDim.x - 1 - blockIdx.x;   // longest first
    const int head = blockIdx.y;

    const float* Qh = Q + ((size_t)head * SEQ + qblk * 64) * HDIM;
    for (int i = tid; i < 64 * 16; i += 256) {
        const int r = i >> 4, d4 = (i & 15) << 2;
        float4 v = *(const float4*)(Qh + r * HDIM + d4);
        sQ[r * FP + d4 + 0] = f2t(v.x);
        sQ[r * FP + d4 + 1] = f2t(v.y);
        sQ[r * FP + d4 + 2] = f2t(v.z);
        sQ[r * FP + d4 + 3] = f2t(v.w);
    }
    if (tid < 64) { sM[tid] = -INFINITY; sL[tid] = 0.f; }

    float o[4][4];
#pragma unroll
    for (int nt = 0; nt < 4; nt++)
#pragma unroll
        for (int i = 0; i < 4; i++) o[nt][i] = 0.f;

    __syncthreads();

    for (int kb = 0; kb <= qblk; kb++) {
        const float* Kh = K + ((size_t)head * SEQ + kb * 64) * HDIM;
        const float* Vh = V + ((size_t)head * SEQ + kb * 64) * HDIM;
        for (int i = tid; i < 64 * 16; i += 256) {
            const int r = i >> 4, d4 = (i & 15) << 2;
            float4 kv = *(const float4*)(Kh + r * HDIM + d4);
            sK[r * FP + d4 + 0] = f2t(kv.x);
            sK[r * FP + d4 + 1] = f2t(kv.y);
            sK[r * FP + d4 + 2] = f2t(kv.z);
            sK[r * FP + d4 + 3] = f2t(kv.w);
            float4 vv = *(const float4*)(Vh + r * HDIM + d4);
            sV[(d4 + 0) * FP + r] = f2t(vv.x);
            sV[(d4 + 1) * FP + r] = f2t(vv.y);
            sV[(d4 + 2) * FP + r] = f2t(vv.z);
            sV[(d4 + 3) * FP + r] = f2t(vv.w);
        }
        __syncthreads();

        // S = Q K^T
        float sc[4][4];
#pragma unroll
        for (int nt = 0; nt < 4; nt++)
#pragma unroll
            for (int i = 0; i < 4; i++) sc[nt][i] = 0.f;

#pragma unroll
        for (int ks = 0; ks < 8; ks++) {
            const int kk = ks * 8 + t4;
            const int ar = wm * 16 + g4;
            uint32_t a0 = sQ[ar * FP + kk];
            uint32_t a1 = sQ[(ar + 8) * FP + kk];
            uint32_t a2 = sQ[ar * FP + kk + 4];
            uint32_t a3 = sQ[(ar + 8) * FP + kk + 4];
#pragma unroll
            for (int nt = 0; nt < 4; nt++) {
                const int br = wn * 32 + nt * 8 + g4;
                mma8(sc[nt], a0, a1, a2, a3, sK[br * FP + kk], sK[br * FP + kk + 4]);
            }
        }

        // scale + mask + write scores (f32) into sP
        {
            const float scl = 0.125f;   // 1/sqrt(64)
            const int r0 = wm * 16 + g4;
#pragma unroll
            for (int nt = 0; nt < 4; nt++) {
                const int col = wn * 32 + nt * 8 + (t4 << 1);
                if (kb == qblk) {
                    sPf[r0 * FP + col]           = (col     <= r0    ) ? sc[nt][0] * scl : -INFINITY;
                    sPf[r0 * FP + col + 1]       = (col + 1 <= r0    ) ? sc[nt][1] * scl : -INFINITY;
                    sPf[(r0 + 8) * FP + col]     = (col     <= r0 + 8) ? sc[nt][2] * scl : -INFINITY;
                    sPf[(r0 + 8) * FP + col + 1] = (col + 1 <= r0 + 8) ? sc[nt][3] * scl : -INFINITY;
                } else {
                    sPf[r0 * FP + col]           = sc[nt][0] * scl;
                    sPf[r0 * FP + col + 1]       = sc[nt][1] * scl;
                    sPf[(r0 + 8) * FP + col]     = sc[nt][2] * scl;
                    sPf[(r0 + 8) * FP + col + 1] = sc[nt][3] * scl;
                }
            }
        }
        __syncthreads();

        // online softmax: 4 threads per row
        {
            const int r = tid >> 2, qq = tid & 3;
            float* rp = sPf + r * FP + qq * 16;
            float mx = -INFINITY;
#pragma unroll
            for (int j = 0; j < 16; j++) mx = fmaxf(mx, rp[j]);
            mx = fmaxf(mx, __shfl_xor_sync(0xffffffffu, mx, 1));
            mx = fmaxf(mx, __shfl_xor_sync(0xffffffffu, mx, 2));
            const float m_old = sM[r];
            const float m_new = fmaxf(m_old, mx);
            float ls = 0.f;
            uint32_t* ru = sP + r * FP + qq * 16;
#pragma unroll
            for (int j = 0; j < 16; j++) {
                const float p = __expf(rp[j] - m_new);
                ls += p;
                ru[j] = f2t(p);
            }
            ls += __shfl_xor_sync(0xffffffffu, ls, 1);
            ls += __shfl_xor_sync(0xffffffffu, ls, 2);
            if (qq == 0) {
                const float corr = __expf(m_old - m_new);
                sC[r] = corr;
                sL[r] = sL[r] * corr + ls;
                sM[r] = m_new;
            }
        }
        __syncthreads();

        // O = O*corr + P V
        {
            const float cr0 = sC[wm * 16 + g4];
            const float cr1 = sC[wm * 16 + 8 + g4];
#pragma unroll
            for (int nt = 0; nt < 4; nt++) {
                o[nt][0] *= cr0; o[nt][1] *= cr0;
                o[nt][2] *= cr1; o[nt][3] *= cr1;
            }
#pragma unroll
            for (int ks = 0; ks < 8; ks++) {
                const int kk = ks * 8 + t4;
                const int ar = wm * 16 + g4;
                uint32_t a0 = sP[ar * FP + kk];
                uint32_t a1 = sP[(ar + 8) * FP + kk];
                uint32_t a2 = sP[ar * FP + kk + 4];
                uint32_t a3 = sP[(ar + 8) * FP + kk + 4];
#pragma unroll
                for (int nt = 0; nt < 4; nt++) {
                    const int br = wn * 32 + nt * 8 + g4;   // d index
                    mma8(o[nt], a0, a1, a2, a3, sV[br * FP + kk], sV[br * FP + kk + 4]);
                }
            }
        }
        __syncthreads();
    }

    // normalize + store [s][d]
    {
        const int r0 = wm * 16 + g4;
        const float inv0 = 1.f / sL[r0];
        const float inv1 = 1.f / sL[r0 + 8];
#pragma unroll
        for (int nt = 0; nt < 4; nt++) {
            const int col = wn * 32 + nt * 8 + (t4 << 1);
            float* d0 = att + (size_t)(qblk * 64 + r0) * DIM + head * HDIM + col;
            d0[0] = o[nt][0] * inv0; d0[1] = o[nt][1] * inv0;
            float* d1 = att + (size_t)(qblk * 64 + r0 + 8) * DIM + head * HDIM + col;
            d1[0] = o[nt][2] * inv1; d1[1] = o[nt][3] * inv1;
        }
    }
}

// ---------------------------------------------------------------------------
// Launch
// ---------------------------------------------------------------------------
extern "C" void kernel_launch(void* const* d_in, const int* in_sizes, int n_in,
                              void* d_out, int out_size)
{
    const float* x    = (const float*)d_in[0];
    const float* cosT = (const float*)d_in[1];
    const float* sinT = (const float*)d_in[2];
    const float* wq   = (const float*)d_in[4];
    const float* wk   = (const float*)d_in[5];
    const float* wv   = (const float*)d_in[6];
    const float* wo   = (const float*)d_in[7];
    float* out = (float*)d_out;

    float *qp, *kp, *vp, *ap;
    cudaGetSymbolAddress((void**)&qp, g_q);
    cudaGetSymbolAddress((void**)&kp, g_k);
    cudaGetSymbolAddress((void**)&vp, g_v);
    cudaGetSymbolAddress((void**)&ap, g_att);

    cudaFuncSetAttribute(flash_tf32,
                         cudaFuncAttributeMaxDynamicSharedMemorySize, FLASH_SMEM);

    dim3 ggrid(DIM / 128, SEQ / 128);
    gemm_tf32<<<ggrid, 256>>>(x, wq, qp, cosT, sinT, 1);
    gemm_tf32<<<ggrid, 256>>>(x, wk, kp, cosT, sinT, 1);
    gemm_tf32<<<ggrid, 256>>>(x, wv, vp, cosT, sinT, 2);

    dim3 fgrid(SEQ / 64, NH);
    flash_tf32<<<fgrid, 256, FLASH_SMEM>>>(qp, kp, vp, ap);

    gemm_tf32<<<ggrid, 256>>>(ap, wo, out, cosT, sinT, 0);
}

// round 3
// speedup vs baseline: 3.2385x; 1.1873x over previous
#include <cuda_runtime.h>
#include <math.h>
#include <stdint.h>

#define SEQ 4096
#define DIM 1024
#define NH  16
#define HDIM 64

// Scratch
__device__ float g_q[NH * SEQ * HDIM];   // [h][s][hd]
__device__ float g_k[NH * SEQ * HDIM];
__device__ float g_v[NH * SEQ * HDIM];
__device__ float g_att[SEQ * DIM];       // [s][d]

__device__ __forceinline__ uint32_t f2t(float f) {
    uint32_t u;
    asm("cvt.rna.tf32.f32 %0, %1;" : "=r"(u) : "f"(f));
    return u;
}

__device__ __forceinline__ void mma8(float c[4],
    uint32_t a0, uint32_t a1, uint32_t a2, uint32_t a3,
    uint32_t b0, uint32_t b1)
{
    asm volatile(
        "mma.sync.aligned.m16n8k8.row.col.f32.tf32.tf32.f32 "
        "{%0,%1,%2,%3},{%4,%5,%6,%7},{%8,%9},{%0,%1,%2,%3};"
        : "+f"(c[0]), "+f"(c[1]), "+f"(c[2]), "+f"(c[3])
        : "r"(a0), "r"(a1), "r"(a2), "r"(a3), "r"(b0), "r"(b1));
}

// ---------------------------------------------------------------------------
// TF32 GEMM: C[4096,1024] = A[M,K] * W[N,K]^T   (unchanged from R2)
// ---------------------------------------------------------------------------
#define BK  16
#define SAS 20

__global__ void __launch_bounds__(256) gemm_tf32(
    const float* __restrict__ A, const float* __restrict__ W,
    float* __restrict__ out,
    const float* __restrict__ cosT, const float* __restrict__ sinT,
    int mode)
{
    __shared__ uint32_t sA[2][128 * SAS];
    __shared__ uint32_t sB[2][128 * SAS];

    const int tid  = threadIdx.x;
    const int lane = tid & 31;
    const int wid  = tid >> 5;
    const int wm   = wid >> 1;
    const int wn   = wid & 1;
    const int g4   = lane >> 2;
    const int t4   = lane & 3;

    const int mBase = blockIdx.y * 128;
    const int nBase = blockIdx.x * 128;

    const int lr = tid >> 2;
    const int lk = (tid & 3) << 2;

    const float* Ag = A + (size_t)(mBase + lr) * DIM + lk;
    const float* Wg = W + (size_t)(nBase + lr) * DIM + lk;

    float c[2][8][4];
#pragma unroll
    for (int mt = 0; mt < 2; mt++)
#pragma unroll
        for (int nt = 0; nt < 8; nt++)
#pragma unroll
            for (int i = 0; i < 4; i++) c[mt][nt][i] = 0.f;

    float4 pa0, pa1, pb0, pb1;
    pa0 = *(const float4*)(Ag);
    pa1 = *(const float4*)(Ag + (size_t)64 * DIM);
    pb0 = *(const float4*)(Wg);
    pb1 = *(const float4*)(Wg + (size_t)64 * DIM);

    {
        uint32_t* a = sA[0]; uint32_t* b = sB[0];
        a[lr * SAS + lk + 0] = f2t(pa0.x); a[lr * SAS + lk + 1] = f2t(pa0.y);
        a[lr * SAS + lk + 2] = f2t(pa0.z); a[lr * SAS + lk + 3] = f2t(pa0.w);
        a[(lr + 64) * SAS + lk + 0] = f2t(pa1.x); a[(lr + 64) * SAS + lk + 1] = f2t(pa1.y);
        a[(lr + 64) * SAS + lk + 2] = f2t(pa1.z); a[(lr + 64) * SAS + lk + 3] = f2t(pa1.w);
        b[lr * SAS + lk + 0] = f2t(pb0.x); b[lr * SAS + lk + 1] = f2t(pb0.y);
        b[lr * SAS + lk + 2] = f2t(pb0.z); b[lr * SAS + lk + 3] = f2t(pb0.w);
        b[(lr + 64) * SAS + lk + 0] = f2t(pb1.x); b[(lr + 64) * SAS + lk + 1] = f2t(pb1.y);
        b[(lr + 64) * SAS + lk + 2] = f2t(pb1.z); b[(lr + 64) * SAS + lk + 3] = f2t(pb1.w);
    }
    __syncthreads();

    const int NCHUNK = DIM / BK;
    for (int ch = 0; ch < NCHUNK; ch++) {
        const int cur = ch & 1;
        if (ch + 1 < NCHUNK) {
            const int off = (ch + 1) * BK;
            pa0 = *(const float4*)(Ag + off);
            pa1 = *(const float4*)(Ag + (size_t)64 * DIM + off);
            pb0 = *(const float4*)(Wg + off);
            pb1 = *(const float4*)(Wg + (size_t)64 * DIM + off);
        }

        const uint32_t* a_s = sA[cur];
        const uint32_t* b_s = sB[cur];
#pragma unroll
        for (int ks = 0; ks < 2; ks++) {
            const int kk = ks * 8 + t4;
            uint32_t af[2][4], bf[8][2];
#pragma unroll
            for (int mt = 0; mt < 2; mt++) {
                const int r = wm * 32 + mt * 16 + g4;
                af[mt][0] = a_s[r * SAS + kk];
                af[mt][1] = a_s[(r + 8) * SAS + kk];
                af[mt][2] = a_s[r * SAS + kk + 4];
                af[mt][3] = a_s[(r + 8) * SAS + kk + 4];
            }
#pragma unroll
            for (int nt = 0; nt < 8; nt++) {
                const int r = wn * 64 + nt * 8 + g4;
                bf[nt][0] = b_s[r * SAS + kk];
                bf[nt][1] = b_s[r * SAS + kk + 4];
            }
#pragma unroll
            for (int mt = 0; mt < 2; mt++)
#pragma unroll
                for (int nt = 0; nt < 8; nt++)
                    mma8(c[mt][nt], af[mt][0], af[mt][1], af[mt][2], af[mt][3],
                         bf[nt][0], bf[nt][1]);
        }

        if (ch + 1 < NCHUNK) {
            const int nb = cur ^ 1;
            uint32_t* a = sA[nb]; uint32_t* b = sB[nb];
            a[lr * SAS + lk + 0] = f2t(pa0.x); a[lr * SAS + lk + 1] = f2t(pa0.y);
            a[lr * SAS + lk + 2] = f2t(pa0.z); a[lr * SAS + lk + 3] = f2t(pa0.w);
            a[(lr + 64) * SAS + lk + 0] = f2t(pa1.x); a[(lr + 64) * SAS + lk + 1] = f2t(pa1.y);
            a[(lr + 64) * SAS + lk + 2] = f2t(pa1.z); a[(lr + 64) * SAS + lk + 3] = f2t(pa1.w);
            b[lr * SAS + lk + 0] = f2t(pb0.x); b[lr * SAS + lk + 1] = f2t(pb0.y);
            b[lr * SAS + lk + 2] = f2t(pb0.z); b[lr * SAS + lk + 3] = f2t(pb0.w);
            b[(lr + 64) * SAS + lk + 0] = f2t(pb1.x); b[(lr + 64) * SAS + lk + 1] = f2t(pb1.y);
            b[(lr + 64) * SAS + lk + 2] = f2t(pb1.z); b[(lr + 64) * SAS + lk + 3] = f2t(pb1.w);
            __syncthreads();
        }
    }

#pragma unroll
    for (int mt = 0; mt < 2; mt++) {
        const int r0 = mBase + wm * 32 + mt * 16 + g4;
#pragma unroll
        for (int nt = 0; nt < 8; nt++) {
            const int colg = nBase + wn * 64 + nt * 8 + (t4 << 1);
            const float* cc = c[mt][nt];
            if (mode == 0) {
                *(float2*)(out + (size_t)r0 * DIM + colg)       = make_float2(cc[0], cc[1]);
                *(float2*)(out + (size_t)(r0 + 8) * DIM + colg) = make_float2(cc[2], cc[3]);
            } else {
                const int head = colg >> 6;
                const int hd   = colg & 63;
                const int f    = hd >> 1;
#pragma unroll
                for (int h = 0; h < 2; h++) {
                    const int row = r0 + h * 8;
                    float e = cc[h * 2 + 0], o = cc[h * 2 + 1];
                    float re = e, ro = o;
                    if (mode == 1) {
                        const float cth = cosT[row * 32 + f];
                        const float sth = sinT[row * 32 + f];
                        re = e * cth - o * sth;
                        ro = e * sth + o * cth;
                    }
                    float* dst = out + ((size_t)head * SEQ + row) * HDIM + hd;
                    dst[0] = re; dst[1] = ro;
                }
            }
        }
    }
}

// ---------------------------------------------------------------------------
// Register-resident TF32 flash attention (FA2-style).
// CTA = 128 threads (4 warps), 64 queries/CTA, 16 rows/warp.
// Q, S/P, O all in registers. Only K [k][d] and V [d][k] in smem.
// ---------------------------------------------------------------------------
#define FP 68
#define FLASH_SMEM (2 * 64 * FP * (int)sizeof(uint32_t))

__global__ void __launch_bounds__(128, 3) flash_reg(
    const float* __restrict__ Q, const float* __restrict__ K,
    const float* __restrict__ V, float* __restrict__ att)
{
    extern __shared__ uint32_t fsm[];
    uint32_t* sK = fsm;            // [key][d] tf32
    uint32_t* sV = sK + 64 * FP;   // [d][key] tf32

    const int tid  = threadIdx.x;
    const int lane = tid & 31;
    const int wid  = tid >> 5;     // 0..3 : rows wid*16 .. wid*16+15
    const int g4   = lane >> 2;    // 0..7
    const int t4   = lane & 3;     // 0..3

    const int qblk = gridDim.x - 1 - blockIdx.x;   // longest first
    const int head = blockIdx.y;

    // --- Stage Q (scaled by 1/sqrt(64)) through sK, pull fragments to regs ---
    const float* Qh = Q + ((size_t)head * SEQ + qblk * 64) * HDIM;
    for (int i = tid; i < 64 * 16; i += 128) {
        const int r = i >> 4, d4 = (i & 15) << 2;
        float4 v = *(const float4*)(Qh + r * HDIM + d4);
        sK[r * FP + d4 + 0] = f2t(v.x * 0.125f);
        sK[r * FP + d4 + 1] = f2t(v.y * 0.125f);
        sK[r * FP + d4 + 2] = f2t(v.z * 0.125f);
        sK[r * FP + d4 + 3] = f2t(v.w * 0.125f);
    }
    __syncthreads();

    uint32_t qf[8][4];
    {
        const int r0 = wid * 16 + g4;
#pragma unroll
        for (int kk = 0; kk < 8; kk++) {
            qf[kk][0] = sK[r0 * FP + kk * 8 + t4];
            qf[kk][1] = sK[(r0 + 8) * FP + kk * 8 + t4];
            qf[kk][2] = sK[r0 * FP + kk * 8 + t4 + 4];
            qf[kk][3] = sK[(r0 + 8) * FP + kk * 8 + t4 + 4];
        }
    }

    float o[8][4];
#pragma unroll
    for (int nt = 0; nt < 8; nt++)
#pragma unroll
        for (int i = 0; i < 4; i++) o[nt][i] = 0.f;

    float m0 = -INFINITY, m1 = -INFINITY, l0 = 0.f, l1 = 0.f;

    const int srcA = (lane & 28) | (t4 >> 1);
    const int srcB = srcA + 2;
    const bool odd = (t4 & 1);

    for (int kb = 0; kb <= qblk; kb++) {
        __syncthreads();   // previous iter's PV reads done before overwrite

        const float* Kh = K + ((size_t)head * SEQ + kb * 64) * HDIM;
        const float* Vh = V + ((size_t)head * SEQ + kb * 64) * HDIM;
        for (int i = tid; i < 64 * 16; i += 128) {
            const int r = i >> 4, d4 = (i & 15) << 2;
            float4 kv = *(const float4*)(Kh + r * HDIM + d4);
            sK[r * FP + d4 + 0] = f2t(kv.x);
            sK[r * FP + d4 + 1] = f2t(kv.y);
            sK[r * FP + d4 + 2] = f2t(kv.z);
            sK[r * FP + d4 + 3] = f2t(kv.w);
            float4 vv = *(const float4*)(Vh + r * HDIM + d4);
            sV[(d4 + 0) * FP + r] = f2t(vv.x);
            sV[(d4 + 1) * FP + r] = f2t(vv.y);
            sV[(d4 + 2) * FP + r] = f2t(vv.z);
            sV[(d4 + 3) * FP + r] = f2t(vv.w);
        }
        __syncthreads();

        // ---- S = Q K^T (scaled) : sc[nt][0..3] in registers ----
        float sc[8][4];
#pragma unroll
        for (int nt = 0; nt < 8; nt++)
#pragma unroll
            for (int i = 0; i < 4; i++) sc[nt][i] = 0.f;

        const uint32_t* kbase = sK + g4 * FP + t4;
#pragma unroll
        for (int kk = 0; kk < 8; kk++) {
#pragma unroll
            for (int nt = 0; nt < 8; nt++) {
                const uint32_t* bp = kbase + nt * 8 * FP + kk * 8;
                mma8(sc[nt], qf[kk][0], qf[kk][1], qf[kk][2], qf[kk][3],
                     bp[0], bp[4]);
            }
        }

        // ---- causal mask on diagonal tile ----
        if (kb == qblk) {
            const int r0 = wid * 16 + g4;
            const int r1 = r0 + 8;
#pragma unroll
            for (int nt = 0; nt < 8; nt++) {
                const int col = nt * 8 + (t4 << 1);
                if (col > r0)     sc[nt][0] = -INFINITY;
                if (col + 1 > r0) sc[nt][1] = -INFINITY;
                if (col > r1)     sc[nt][2] = -INFINITY;
                if (col + 1 > r1) sc[nt][3] = -INFINITY;
            }
        }

        // ---- online softmax in registers (rows live within quads) ----
        float mx0 = -INFINITY, mx1 = -INFINITY;
#pragma unroll
        for (int nt = 0; nt < 8; nt++) {
            mx0 = fmaxf(mx0, fmaxf(sc[nt][0], sc[nt][1]));
            mx1 = fmaxf(mx1, fmaxf(sc[nt][2], sc[nt][3]));
        }
        mx0 = fmaxf(mx0, __shfl_xor_sync(0xffffffffu, mx0, 1));
        mx0 = fmaxf(mx0, __shfl_xor_sync(0xffffffffu, mx0, 2));
        mx1 = fmaxf(mx1, __shfl_xor_sync(0xffffffffu, mx1, 1));
        mx1 = fmaxf(mx1, __shfl_xor_sync(0xffffffffu, mx1, 2));

        const float mn0 = fmaxf(m0, mx0);
        const float mn1 = fmaxf(m1, mx1);
        const float corr0 = __expf(m0 - mn0);
        const float corr1 = __expf(m1 - mn1);
        m0 = mn0; m1 = mn1;

        float ls0 = 0.f, ls1 = 0.f;
#pragma unroll
        for (int nt = 0; nt < 8; nt++) {
            sc[nt][0] = __expf(sc[nt][0] - mn0);
            sc[nt][1] = __expf(sc[nt][1] - mn0);
            sc[nt][2] = __expf(sc[nt][2] - mn1);
            sc[nt][3] = __expf(sc[nt][3] - mn1);
            ls0 += sc[nt][0] + sc[nt][1];
            ls1 += sc[nt][2] + sc[nt][3];
        }
        ls0 += __shfl_xor_sync(0xffffffffu, ls0, 1);
        ls0 += __shfl_xor_sync(0xffffffffu, ls0, 2);
        ls1 += __shfl_xor_sync(0xffffffffu, ls1, 1);
        ls1 += __shfl_xor_sync(0xffffffffu, ls1, 2);
        l0 = l0 * corr0 + ls0;
        l1 = l1 * corr1 + ls1;

#pragma unroll
        for (int nt = 0; nt < 8; nt++) {
            o[nt][0] *= corr0; o[nt][1] *= corr0;
            o[nt][2] *= corr1; o[nt][3] *= corr1;
        }

        // ---- O += P V : shuffle P C-fragments into A-fragments ----
        const uint32_t* vbase = sV + g4 * FP + t4;
#pragma unroll
        for (int kk = 0; kk < 8; kk++) {
            const float v0 = __shfl_sync(0xffffffffu, sc[kk][0], srcA);
            const float v1 = __shfl_sync(0xffffffffu, sc[kk][1], srcA);
            const float v2 = __shfl_sync(0xffffffffu, sc[kk][2], srcA);
            const float v3 = __shfl_sync(0xffffffffu, sc[kk][3], srcA);
            const float v4 = __shfl_sync(0xffffffffu, sc[kk][0], srcB);
            const float v5 = __shfl_sync(0xffffffffu, sc[kk][1], srcB);
            const float v6 = __shfl_sync(0xffffffffu, sc[kk][2], srcB);
            const float v7 = __shfl_sync(0xffffffffu, sc[kk][3], srcB);
            const uint32_t a0 = f2t(odd ? v1 : v0);
            const uint32_t a1 = f2t(odd ? v3 : v2);
            const uint32_t a2 = f2t(odd ? v5 : v4);
            const uint32_t a3 = f2t(odd ? v7 : v6);
#pragma unroll
            for (int nt = 0; nt < 8; nt++) {
                const uint32_t* bp = vbase + nt * 8 * FP + kk * 8;
                mma8(o[nt], a0, a1, a2, a3, bp[0], bp[4]);
            }
        }
    }

    // ---- epilogue: normalize, store to [s][d] ----
    {
        const float inv0 = 1.f / l0;
        const float inv1 = 1.f / l1;
        const int r0 = qblk * 64 + wid * 16 + g4;
#pragma unroll
        for (int nt = 0; nt < 8; nt++) {
            const int col = head * HDIM + nt * 8 + (t4 << 1);
            *(float2*)(att + (size_t)r0 * DIM + col) =
                make_float2(o[nt][0] * inv0, o[nt][1] * inv0);
            *(float2*)(att + (size_t)(r0 + 8) * DIM + col) =
                make_float2(o[nt][2] * inv1, o[nt][3] * inv1);
        }
    }
}

// ---------------------------------------------------------------------------
// Launch
// ---------------------------------------------------------------------------
extern "C" void kernel_launch(void* const* d_in, const int* in_sizes, int n_in,
                              void* d_out, int out_size)
{
    const float* x    = (const float*)d_in[0];
    const float* cosT = (const float*)d_in[1];
    const float* sinT = (const float*)d_in[2];
    const float* wq   = (const float*)d_in[4];
    const float* wk   = (const float*)d_in[5];
    const float* wv   = (const float*)d_in[6];
    const float* wo   = (const float*)d_in[7];
    float* out = (float*)d_out;

    float *qp, *kp, *vp, *ap;
    cudaGetSymbolAddress((void**)&qp, g_q);
    cudaGetSymbolAddress((void**)&kp, g_k);
    cudaGetSymbolAddress((void**)&vp, g_v);
    cudaGetSymbolAddress((void**)&ap, g_att);

    cudaFuncSetAttribute(flash_reg,
                         cudaFuncAttributeMaxDynamicSharedMemorySize, FLASH_SMEM);

    dim3 ggrid(DIM / 128, SEQ / 128);
    gemm_tf32<<<ggrid, 256>>>(x, wq, qp, cosT, sinT, 1);
    gemm_tf32<<<ggrid, 256>>>(x, wk, kp, cosT, sinT, 1);
    gemm_tf32<<<ggrid, 256>>>(x, wv, vp, cosT, sinT, 2);

    dim3 fgrid(SEQ / 64, NH);
    flash_reg<<<fgrid, 128, FLASH_SMEM>>>(qp, kp, vp, ap);

    gemm_tf32<<<ggrid, 256>>>(ap, wo, out, cosT, sinT, 0);
}

// round 4
// speedup vs baseline: 3.5359x; 1.0918x over previous
#include <cuda_runtime.h>
#include <math.h>
#include <stdint.h>

#define SEQ 4096
#define DIM 1024
#define NH  16
#define HDIM 64

// Scratch
__device__ float g_q[NH * SEQ * HDIM];   // [h][s][hd]
__device__ float g_k[NH * SEQ * HDIM];
__device__ float g_v[NH * SEQ * HDIM];
__device__ float g_att[SEQ * DIM];       // [s][d]

__device__ __forceinline__ uint32_t f2t(float f) {
    uint32_t u;
    asm("cvt.rna.tf32.f32 %0, %1;" : "=r"(u) : "f"(f));
    return u;
}

__device__ __forceinline__ float ex2(float x) {
    float r;
    asm("ex2.approx.f32 %0, %1;" : "=f"(r) : "f"(x));
    return r;
}

__device__ __forceinline__ void mma8(float c[4],
    uint32_t a0, uint32_t a1, uint32_t a2, uint32_t a3,
    uint32_t b0, uint32_t b1)
{
    asm volatile(
        "mma.sync.aligned.m16n8k8.row.col.f32.tf32.tf32.f32 "
        "{%0,%1,%2,%3},{%4,%5,%6,%7},{%8,%9},{%0,%1,%2,%3};"
        : "+f"(c[0]), "+f"(c[1]), "+f"(c[2]), "+f"(c[3])
        : "r"(a0), "r"(a1), "r"(a2), "r"(a3), "r"(b0), "r"(b1));
}

// ---------------------------------------------------------------------------
// TF32 GEMM: C[4096,1024] = A[M,K] * W[N,K]^T   (unchanged from R2)
// ---------------------------------------------------------------------------
#define BK  16
#define SAS 20

__global__ void __launch_bounds__(256) gemm_tf32(
    const float* __restrict__ A, const float* __restrict__ W,
    float* __restrict__ out,
    const float* __restrict__ cosT, const float* __restrict__ sinT,
    int mode)
{
    __shared__ uint32_t sA[2][128 * SAS];
    __shared__ uint32_t sB[2][128 * SAS];

    const int tid  = threadIdx.x;
    const int lane = tid & 31;
    const int wid  = tid >> 5;
    const int wm   = wid >> 1;
    const int wn   = wid & 1;
    const int g4   = lane >> 2;
    const int t4   = lane & 3;

    const int mBase = blockIdx.y * 128;
    const int nBase = blockIdx.x * 128;

    const int lr = tid >> 2;
    const int lk = (tid & 3) << 2;

    const float* Ag = A + (size_t)(mBase + lr) * DIM + lk;
    const float* Wg = W + (size_t)(nBase + lr) * DIM + lk;

    float c[2][8][4];
#pragma unroll
    for (int mt = 0; mt < 2; mt++)
#pragma unroll
        for (int nt = 0; nt < 8; nt++)
#pragma unroll
            for (int i = 0; i < 4; i++) c[mt][nt][i] = 0.f;

    float4 pa0, pa1, pb0, pb1;
    pa0 = *(const float4*)(Ag);
    pa1 = *(const float4*)(Ag + (size_t)64 * DIM);
    pb0 = *(const float4*)(Wg);
    pb1 = *(const float4*)(Wg + (size_t)64 * DIM);

    {
        uint32_t* a = sA[0]; uint32_t* b = sB[0];
        a[lr * SAS + lk + 0] = f2t(pa0.x); a[lr * SAS + lk + 1] = f2t(pa0.y);
        a[lr * SAS + lk + 2] = f2t(pa0.z); a[lr * SAS + lk + 3] = f2t(pa0.w);
        a[(lr + 64) * SAS + lk + 0] = f2t(pa1.x); a[(lr + 64) * SAS + lk + 1] = f2t(pa1.y);
        a[(lr + 64) * SAS + lk + 2] = f2t(pa1.z); a[(lr + 64) * SAS + lk + 3] = f2t(pa1.w);
        b[lr * SAS + lk + 0] = f2t(pb0.x); b[lr * SAS + lk + 1] = f2t(pb0.y);
        b[lr * SAS + lk + 2] = f2t(pb0.z); b[lr * SAS + lk + 3] = f2t(pb0.w);
        b[(lr + 64) * SAS + lk + 0] = f2t(pb1.x); b[(lr + 64) * SAS + lk + 1] = f2t(pb1.y);
        b[(lr + 64) * SAS + lk + 2] = f2t(pb1.z); b[(lr + 64) * SAS + lk + 3] = f2t(pb1.w);
    }
    __syncthreads();

    const int NCHUNK = DIM / BK;
    for (int ch = 0; ch < NCHUNK; ch++) {
        const int cur = ch & 1;
        if (ch + 1 < NCHUNK) {
            const int off = (ch + 1) * BK;
            pa0 = *(const float4*)(Ag + off);
            pa1 = *(const float4*)(Ag + (size_t)64 * DIM + off);
            pb0 = *(const float4*)(Wg + off);
            pb1 = *(const float4*)(Wg + (size_t)64 * DIM + off);
        }

        const uint32_t* a_s = sA[cur];
        const uint32_t* b_s = sB[cur];
#pragma unroll
        for (int ks = 0; ks < 2; ks++) {
            const int kk = ks * 8 + t4;
            uint32_t af[2][4], bf[8][2];
#pragma unroll
            for (int mt = 0; mt < 2; mt++) {
                const int r = wm * 32 + mt * 16 + g4;
                af[mt][0] = a_s[r * SAS + kk];
                af[mt][1] = a_s[(r + 8) * SAS + kk];
                af[mt][2] = a_s[r * SAS + kk + 4];
                af[mt][3] = a_s[(r + 8) * SAS + kk + 4];
            }
#pragma unroll
            for (int nt = 0; nt < 8; nt++) {
                const int r = wn * 64 + nt * 8 + g4;
                bf[nt][0] = b_s[r * SAS + kk];
                bf[nt][1] = b_s[r * SAS + kk + 4];
            }
#pragma unroll
            for (int mt = 0; mt < 2; mt++)
#pragma unroll
                for (int nt = 0; nt < 8; nt++)
                    mma8(c[mt][nt], af[mt][0], af[mt][1], af[mt][2], af[mt][3],
                         bf[nt][0], bf[nt][1]);
        }

        if (ch + 1 < NCHUNK) {
            const int nb = cur ^ 1;
            uint32_t* a = sA[nb]; uint32_t* b = sB[nb];
            a[lr * SAS + lk + 0] = f2t(pa0.x); a[lr * SAS + lk + 1] = f2t(pa0.y);
            a[lr * SAS + lk + 2] = f2t(pa0.z); a[lr * SAS + lk + 3] = f2t(pa0.w);
            a[(lr + 64) * SAS + lk + 0] = f2t(pa1.x); a[(lr + 64) * SAS + lk + 1] = f2t(pa1.y);
            a[(lr + 64) * SAS + lk + 2] = f2t(pa1.z); a[(lr + 64) * SAS + lk + 3] = f2t(pa1.w);
            b[lr * SAS + lk + 0] = f2t(pb0.x); b[lr * SAS + lk + 1] = f2t(pb0.y);
            b[lr * SAS + lk + 2] = f2t(pb0.z); b[lr * SAS + lk + 3] = f2t(pb0.w);
            b[(lr + 64) * SAS + lk + 0] = f2t(pb1.x); b[(lr + 64) * SAS + lk + 1] = f2t(pb1.y);
            b[(lr + 64) * SAS + lk + 2] = f2t(pb1.z); b[(lr + 64) * SAS + lk + 3] = f2t(pb1.w);
            __syncthreads();
        }
    }

#pragma unroll
    for (int mt = 0; mt < 2; mt++) {
        const int r0 = mBase + wm * 32 + mt * 16 + g4;
#pragma unroll
        for (int nt = 0; nt < 8; nt++) {
            const int colg = nBase + wn * 64 + nt * 8 + (t4 << 1);
            const float* cc = c[mt][nt];
            if (mode == 0) {
                *(float2*)(out + (size_t)r0 * DIM + colg)       = make_float2(cc[0], cc[1]);
                *(float2*)(out + (size_t)(r0 + 8) * DIM + colg) = make_float2(cc[2], cc[3]);
            } else {
                const int head = colg >> 6;
                const int hd   = colg & 63;
                const int f    = hd >> 1;
#pragma unroll
                for (int h = 0; h < 2; h++) {
                    const int row = r0 + h * 8;
                    float e = cc[h * 2 + 0], o = cc[h * 2 + 1];
                    float re = e, ro = o;
                    if (mode == 1) {
                        const float cth = cosT[row * 32 + f];
                        const float sth = sinT[row * 32 + f];
                        re = e * cth - o * sth;
                        ro = e * sth + o * cth;
                    }
                    float* dst = out + ((size_t)head * SEQ + row) * HDIM + hd;
                    dst[0] = re; dst[1] = ro;
                }
            }
        }
    }
}

// ---------------------------------------------------------------------------
// Register-resident TF32 flash attention, M=32 warp tile.
// CTA = 128 threads (4 warps), 128 queries/CTA, 32 rows/warp (2 m-halves).
// Each K/V B-fragment is loaded from smem ONCE and feeds both m-halves.
// Softmax in log2 domain (scale folded into Q).
// ---------------------------------------------------------------------------
#define FP 68
#define FLASH_SMEM (2 * 64 * FP * (int)sizeof(uint32_t))
#define QSCALE (0.125f * 1.4426950408889634f)   // 1/sqrt(64) * log2(e)

__global__ void __launch_bounds__(128, 2) flash_reg(
    const float* __restrict__ Q, const float* __restrict__ K,
    const float* __restrict__ V, float* __restrict__ att)
{
    extern __shared__ uint32_t fsm[];
    uint32_t* sK = fsm;            // [key][d] tf32
    uint32_t* sV = sK + 64 * FP;   // [d][key] tf32

    const int tid  = threadIdx.x;
    const int lane = tid & 31;
    const int wid  = tid >> 5;     // warp owns rows wid*32 .. wid*32+31
    const int g4   = lane >> 2;    // 0..7
    const int t4   = lane & 3;     // 0..3

    const int qblk = gridDim.x - 1 - blockIdx.x;   // longest first
    const int head = blockIdx.y;

    // --- Q fragments for both m-halves, direct from global, scaled ---
    const float* Qh = Q + ((size_t)head * SEQ + qblk * 128) * HDIM;
    uint32_t qf[8][2][4];
#pragma unroll
    for (int kk = 0; kk < 8; kk++)
#pragma unroll
        for (int mh = 0; mh < 2; mh++) {
            const int r = wid * 32 + mh * 16 + g4;
            const int d = kk * 8 + t4;
            qf[kk][mh][0] = f2t(Qh[(size_t)r * HDIM + d] * QSCALE);
            qf[kk][mh][1] = f2t(Qh[(size_t)(r + 8) * HDIM + d] * QSCALE);
            qf[kk][mh][2] = f2t(Qh[(size_t)r * HDIM + d + 4] * QSCALE);
            qf[kk][mh][3] = f2t(Qh[(size_t)(r + 8) * HDIM + d + 4] * QSCALE);
        }

    float o[2][8][4];
#pragma unroll
    for (int mh = 0; mh < 2; mh++)
#pragma unroll
        for (int nt = 0; nt < 8; nt++)
#pragma unroll
            for (int i = 0; i < 4; i++) o[mh][nt][i] = 0.f;

    float m[2][2], l[2][2];
#pragma unroll
    for (int mh = 0; mh < 2; mh++) {
        m[mh][0] = -INFINITY; m[mh][1] = -INFINITY;
        l[mh][0] = 0.f;       l[mh][1] = 0.f;
    }

    const int srcA = (lane & 28) | (t4 >> 1);
    const int srcB = srcA + 2;
    const bool odd = (t4 & 1);

    const int nkb = 2 * qblk + 2;   // key tiles of 64
    for (int kb = 0; kb < nkb; kb++) {
        __syncthreads();

        const float* Kh = K + ((size_t)head * SEQ + kb * 64) * HDIM;
        const float* Vh = V + ((size_t)head * SEQ + kb * 64) * HDIM;
        for (int i = tid; i < 64 * 16; i += 128) {
            const int r = i >> 4, d4 = (i & 15) << 2;
            float4 kv = *(const float4*)(Kh + r * HDIM + d4);
            sK[r * FP + d4 + 0] = f2t(kv.x);
            sK[r * FP + d4 + 1] = f2t(kv.y);
            sK[r * FP + d4 + 2] = f2t(kv.z);
            sK[r * FP + d4 + 3] = f2t(kv.w);
            float4 vv = *(const float4*)(Vh + r * HDIM + d4);
            sV[(d4 + 0) * FP + r] = f2t(vv.x);
            sV[(d4 + 1) * FP + r] = f2t(vv.y);
            sV[(d4 + 2) * FP + r] = f2t(vv.z);
            sV[(d4 + 3) * FP + r] = f2t(vv.w);
        }
        __syncthreads();

        // ---- S = Q K^T : B fragments loaded once, used by both m-halves ----
        float sc[2][8][4];
#pragma unroll
        for (int mh = 0; mh < 2; mh++)
#pragma unroll
            for (int nt = 0; nt < 8; nt++)
#pragma unroll
                for (int i = 0; i < 4; i++) sc[mh][nt][i] = 0.f;

        const uint32_t* kbase = sK + g4 * FP + t4;
#pragma unroll
        for (int kk = 0; kk < 8; kk++) {
#pragma unroll
            for (int nt = 0; nt < 8; nt++) {
                const uint32_t* bp = kbase + nt * 8 * FP + kk * 8;
                const uint32_t b0 = bp[0], b1 = bp[4];
                mma8(sc[0][nt], qf[kk][0][0], qf[kk][0][1], qf[kk][0][2], qf[kk][0][3], b0, b1);
                mma8(sc[1][nt], qf[kk][1][0], qf[kk][1][1], qf[kk][1][2], qf[kk][1][3], b0, b1);
            }
        }

        // ---- causal mask (only last two tiles can cross the diagonal) ----
        if (kb >= 2 * qblk) {
#pragma unroll
            for (int mh = 0; mh < 2; mh++) {
                const int r0 = qblk * 128 + wid * 32 + mh * 16 + g4;
                const int r1 = r0 + 8;
#pragma unroll
                for (int nt = 0; nt < 8; nt++) {
                    const int col = kb * 64 + nt * 8 + (t4 << 1);
                    if (col > r0)     sc[mh][nt][0] = -INFINITY;
                    if (col + 1 > r0) sc[mh][nt][1] = -INFINITY;
                    if (col > r1)     sc[mh][nt][2] = -INFINITY;
                    if (col + 1 > r1) sc[mh][nt][3] = -INFINITY;
                }
            }
        }

        // ---- online softmax in log2 domain, per m-half ----
        float corr[2][2];
#pragma unroll
        for (int mh = 0; mh < 2; mh++) {
            float mx0 = -INFINITY, mx1 = -INFINITY;
#pragma unroll
            for (int nt = 0; nt < 8; nt++) {
                mx0 = fmaxf(mx0, fmaxf(sc[mh][nt][0], sc[mh][nt][1]));
                mx1 = fmaxf(mx1, fmaxf(sc[mh][nt][2], sc[mh][nt][3]));
            }
            mx0 = fmaxf(mx0, __shfl_xor_sync(0xffffffffu, mx0, 1));
            mx0 = fmaxf(mx0, __shfl_xor_sync(0xffffffffu, mx0, 2));
            mx1 = fmaxf(mx1, __shfl_xor_sync(0xffffffffu, mx1, 1));
            mx1 = fmaxf(mx1, __shfl_xor_sync(0xffffffffu, mx1, 2));

            const float mn0 = fmaxf(m[mh][0], mx0);
            const float mn1 = fmaxf(m[mh][1], mx1);
            corr[mh][0] = ex2(m[mh][0] - mn0);
            corr[mh][1] = ex2(m[mh][1] - mn1);
            m[mh][0] = mn0; m[mh][1] = mn1;

            float ls0 = 0.f, ls1 = 0.f;
#pragma unroll
            for (int nt = 0; nt < 8; nt++) {
                sc[mh][nt][0] = ex2(sc[mh][nt][0] - mn0);
                sc[mh][nt][1] = ex2(sc[mh][nt][1] - mn0);
                sc[mh][nt][2] = ex2(sc[mh][nt][2] - mn1);
                sc[mh][nt][3] = ex2(sc[mh][nt][3] - mn1);
                ls0 += sc[mh][nt][0] + sc[mh][nt][1];
                ls1 += sc[mh][nt][2] + sc[mh][nt][3];
            }
            ls0 += __shfl_xor_sync(0xffffffffu, ls0, 1);
            ls0 += __shfl_xor_sync(0xffffffffu, ls0, 2);
            ls1 += __shfl_xor_sync(0xffffffffu, ls1, 1);
            ls1 += __shfl_xor_sync(0xffffffffu, ls1, 2);
            l[mh][0] = l[mh][0] * corr[mh][0] + ls0;
            l[mh][1] = l[mh][1] * corr[mh][1] + ls1;

#pragma unroll
            for (int nt = 0; nt < 8; nt++) {
                o[mh][nt][0] *= corr[mh][0]; o[mh][nt][1] *= corr[mh][0];
                o[mh][nt][2] *= corr[mh][1]; o[mh][nt][3] *= corr[mh][1];
            }
        }

        // ---- O += P V : shuffle P into A-fragments; V fragments shared ----
        const uint32_t* vbase = sV + g4 * FP + t4;
#pragma unroll
        for (int kk = 0; kk < 8; kk++) {
            uint32_t pa[2][4];
#pragma unroll
            for (int mh = 0; mh < 2; mh++) {
                const float v0 = __shfl_sync(0xffffffffu, sc[mh][kk][0], srcA);
                const float v1 = __shfl_sync(0xffffffffu, sc[mh][kk][1], srcA);
                const float v2 = __shfl_sync(0xffffffffu, sc[mh][kk][2], srcA);
                const float v3 = __shfl_sync(0xffffffffu, sc[mh][kk][3], srcA);
                const float v4 = __shfl_sync(0xffffffffu, sc[mh][kk][0], srcB);
                const float v5 = __shfl_sync(0xffffffffu, sc[mh][kk][1], srcB);
                const float v6 = __shfl_sync(0xffffffffu, sc[mh][kk][2], srcB);
                const float v7 = __shfl_sync(0xffffffffu, sc[mh][kk][3], srcB);
                pa[mh][0] = f2t(odd ? v1 : v0);
                pa[mh][1] = f2t(odd ? v3 : v2);
                pa[mh][2] = f2t(odd ? v5 : v4);
                pa[mh][3] = f2t(odd ? v7 : v6);
            }
#pragma unroll
            for (int nt = 0; nt < 8; nt++) {
                const uint32_t* bp = vbase + nt * 8 * FP + kk * 8;
                const uint32_t b0 = bp[0], b1 = bp[4];
                mma8(o[0][nt], pa[0][0], pa[0][1], pa[0][2], pa[0][3], b0, b1);
                mma8(o[1][nt], pa[1][0], pa[1][1], pa[1][2], pa[1][3], b0, b1);
            }
        }
    }

    // ---- epilogue: normalize, store to [s][d] ----
#pragma unroll
    for (int mh = 0; mh < 2; mh++) {
        const float inv0 = 1.f / l[mh][0];
        const float inv1 = 1.f / l[mh][1];
        const int r0 = qblk * 128 + wid * 32 + mh * 16 + g4;
#pragma unroll
        for (int nt = 0; nt < 8; nt++) {
            const int col = head * HDIM + nt * 8 + (t4 << 1);
            *(float2*)(att + (size_t)r0 * DIM + col) =
                make_float2(o[mh][nt][0] * inv0, o[mh][nt][1] * inv0);
            *(float2*)(att + (size_t)(r0 + 8) * DIM + col) =
                make_float2(o[mh][nt][2] * inv1, o[mh][nt][3] * inv1);
        }
    }
}

// ---------------------------------------------------------------------------
// Launch
// ---------------------------------------------------------------------------
extern "C" void kernel_launch(void* const* d_in, const int* in_sizes, int n_in,
                              void* d_out, int out_size)
{
    const float* x    = (const float*)d_in[0];
    const float* cosT = (const float*)d_in[1];
    const float* sinT = (const float*)d_in[2];
    const float* wq   = (const float*)d_in[4];
    const float* wk   = (const float*)d_in[5];
    const float* wv   = (const float*)d_in[6];
    const float* wo   = (const float*)d_in[7];
    float* out = (float*)d_out;

    float *qp, *kp, *vp, *ap;
    cudaGetSymbolAddress((void**)&qp, g_q);
    cudaGetSymbolAddress((void**)&kp, g_k);
    cudaGetSymbolAddress((void**)&vp, g_v);
    cudaGetSymbolAddress((void**)&ap, g_att);

    cudaFuncSetAttribute(flash_reg,
                         cudaFuncAttributeMaxDynamicSharedMemorySize, FLASH_SMEM);

    dim3 ggrid(DIM / 128, SEQ / 128);
    gemm_tf32<<<ggrid, 256>>>(x, wq, qp, cosT, sinT, 1);
    gemm_tf32<<<ggrid, 256>>>(x, wk, kp, cosT, sinT, 1);
    gemm_tf32<<<ggrid, 256>>>(x, wv, vp, cosT, sinT, 2);

    dim3 fgrid(SEQ / 128, NH);
    flash_reg<<<fgrid, 128, FLASH_SMEM>>>(qp, kp, vp, ap);

    gemm_tf32<<<ggrid, 256>>>(ap, wo, out, cosT, sinT, 0);
}

// round 5
// speedup vs baseline: 3.8689x; 1.0942x over previous
#include <cuda_runtime.h>
#include <math.h>
#include <stdint.h>

#define SEQ 4096
#define DIM 1024
#define NH  16
#define HDIM 64

// Scratch (tf32 bits stored as float)
__device__ float g_q[NH * SEQ * HDIM];   // [h][s][hd] tf32, pre-scaled
__device__ float g_k[NH * SEQ * HDIM];   // [h][s][hd] tf32
__device__ float g_v[NH * SEQ * HDIM];   // [h][s][hd] tf32
__device__ float g_att[SEQ * DIM];       // [s][d]     tf32
__device__ float g_xt[SEQ * DIM];        // x   as tf32
__device__ float g_wq[DIM * DIM];        // weights as tf32
__device__ float g_wk[DIM * DIM];
__device__ float g_wv[DIM * DIM];
__device__ float g_wo[DIM * DIM];

#define QSCALE (0.125f * 1.4426950408889634f)   // 1/sqrt(64) * log2(e)

__device__ __forceinline__ uint32_t f2t(float f) {
    uint32_t u;
    asm("cvt.rna.tf32.f32 %0, %1;" : "=r"(u) : "f"(f));
    return u;
}

__device__ __forceinline__ float ex2(float x) {
    float r;
    asm("ex2.approx.f32 %0, %1;" : "=f"(r) : "f"(x));
    return r;
}

__device__ __forceinline__ void mma8(float c[4],
    uint32_t a0, uint32_t a1, uint32_t a2, uint32_t a3,
    uint32_t b0, uint32_t b1)
{
    asm volatile(
        "mma.sync.aligned.m16n8k8.row.col.f32.tf32.tf32.f32 "
        "{%0,%1,%2,%3},{%4,%5,%6,%7},{%8,%9},{%0,%1,%2,%3};"
        : "+f"(c[0]), "+f"(c[1]), "+f"(c[2]), "+f"(c[3])
        : "r"(a0), "r"(a1), "r"(a2), "r"(a3), "r"(b0), "r"(b1));
}

__device__ __forceinline__ void cpa16(uint32_t dst_smem, const void* src) {
    asm volatile("cp.async.cg.shared.global [%0], [%1], 16;"
                 :: "r"(dst_smem), "l"(src));
}
__device__ __forceinline__ void cpa_commit() {
    asm volatile("cp.async.commit_group;");
}
template<int N>
__device__ __forceinline__ void cpa_wait() {
    asm volatile("cp.async.wait_group %0;" :: "n"(N));
}

// ---------------------------------------------------------------------------
// Convert fp32 -> tf32 bits (grid-stride, float4)
// ---------------------------------------------------------------------------
__global__ void cvt_tf32(const float* __restrict__ src, float* __restrict__ dst,
                         int n4)
{
    for (int i = blockIdx.x * blockDim.x + threadIdx.x; i < n4;
         i += gridDim.x * blockDim.x) {
        float4 v = ((const float4*)src)[i];
        v.x = __uint_as_float(f2t(v.x));
        v.y = __uint_as_float(f2t(v.y));
        v.z = __uint_as_float(f2t(v.z));
        v.w = __uint_as_float(f2t(v.w));
        ((float4*)dst)[i] = v;
    }
}

// ---------------------------------------------------------------------------
// TF32 GEMM on pre-converted tf32 data, cp.async 2-stage pipeline.
// C[4096,1024] = A[M,K] * W[N,K]^T
// mode 0: plain f32 out; 1: RoPE+QSCALE -> tf32 [h][s][hd];
// 2: RoPE -> tf32 [h][s][hd]; 3: tf32 [h][s][hd]
// ---------------------------------------------------------------------------
#define BK  16
#define SAS 20

__global__ void __launch_bounds__(256) gemm_tf32(
    const float* __restrict__ A,
    const float* __restrict__ W0, const float* __restrict__ W1,
    const float* __restrict__ W2,
    float* __restrict__ out0, float* __restrict__ out1,
    float* __restrict__ out2,
    const float* __restrict__ cosT, const float* __restrict__ sinT,
    int mode0)
{
    __shared__ uint32_t sA[2][128 * SAS];
    __shared__ uint32_t sB[2][128 * SAS];

    const float* W;
    float* out;
    int mode;
    if (blockIdx.z == 0)      { W = W0; out = out0; mode = mode0; }
    else if (blockIdx.z == 1) { W = W1; out = out1; mode = 2; }
    else                      { W = W2; out = out2; mode = 3; }

    const int tid  = threadIdx.x;
    const int lane = tid & 31;
    const int wid  = tid >> 5;
    const int wm   = wid >> 1;
    const int wn   = wid & 1;
    const int g4   = lane >> 2;
    const int t4   = lane & 3;

    const int mBase = blockIdx.y * 128;
    const int nBase = blockIdx.x * 128;

    const uint32_t sAu = (uint32_t)__cvta_generic_to_shared(&sA[0][0]);
    const uint32_t sBu = (uint32_t)__cvta_generic_to_shared(&sB[0][0]);
    const uint32_t stageBytes = 128 * SAS * 4;

    // prefetch helper data
    const int pr = tid >> 1;            // 0..127 row
    const int pq = (tid & 1) << 3;      // 0 or 8 (two 16B chunks each)

    auto prefetch = [&](int buf, int koff) {
        const uint32_t da = sAu + buf * stageBytes + (pr * SAS + pq) * 4;
        const uint32_t db = sBu + buf * stageBytes + (pr * SAS + pq) * 4;
        const float* gA = A + (size_t)(mBase + pr) * DIM + koff + pq;
        const float* gW = W + (size_t)(nBase + pr) * DIM + koff + pq;
        cpa16(da, gA);     cpa16(da + 16, gA + 4);
        cpa16(db, gW);     cpa16(db + 16, gW + 4);
    };

    float c[2][8][4];
#pragma unroll
    for (int mt = 0; mt < 2; mt++)
#pragma unroll
        for (int nt = 0; nt < 8; nt++)
#pragma unroll
            for (int i = 0; i < 4; i++) c[mt][nt][i] = 0.f;

    const int NCHUNK = DIM / BK;   // 64
    prefetch(0, 0);  cpa_commit();
    prefetch(1, BK); cpa_commit();

    for (int ch = 0; ch < NCHUNK; ch++) {
        if (ch + 1 < NCHUNK) cpa_wait<1>(); else cpa_wait<0>();
        __syncthreads();

        const uint32_t* a_s = sA[ch & 1];
        const uint32_t* b_s = sB[ch & 1];
#pragma unroll
        for (int ks = 0; ks < 2; ks++) {
            const int kk = ks * 8 + t4;
            uint32_t af[2][4], bf[8][2];
#pragma unroll
            for (int mt = 0; mt < 2; mt++) {
                const int r = wm * 32 + mt * 16 + g4;
                af[mt][0] = a_s[r * SAS + kk];
                af[mt][1] = a_s[(r + 8) * SAS + kk];
                af[mt][2] = a_s[r * SAS + kk + 4];
                af[mt][3] = a_s[(r + 8) * SAS + kk + 4];
            }
#pragma unroll
            for (int nt = 0; nt < 8; nt++) {
                const int r = wn * 64 + nt * 8 + g4;
                bf[nt][0] = b_s[r * SAS + kk];
                bf[nt][1] = b_s[r * SAS + kk + 4];
            }
#pragma unroll
            for (int mt = 0; mt < 2; mt++)
#pragma unroll
                for (int nt = 0; nt < 8; nt++)
                    mma8(c[mt][nt], af[mt][0], af[mt][1], af[mt][2], af[mt][3],
                         bf[nt][0], bf[nt][1]);
        }
        __syncthreads();
        if (ch + 2 < NCHUNK) { prefetch(ch & 1, (ch + 2) * BK); cpa_commit(); }
    }

    // Epilogue
#pragma unroll
    for (int mt = 0; mt < 2; mt++) {
        const int r0 = mBase + wm * 32 + mt * 16 + g4;
#pragma unroll
        for (int nt = 0; nt < 8; nt++) {
            const int colg = nBase + wn * 64 + nt * 8 + (t4 << 1);
            const float* cc = c[mt][nt];
            if (mode == 0) {
                *(float2*)(out + (size_t)r0 * DIM + colg)       = make_float2(cc[0], cc[1]);
                *(float2*)(out + (size_t)(r0 + 8) * DIM + colg) = make_float2(cc[2], cc[3]);
            } else {
                const int head = colg >> 6;
                const int hd   = colg & 63;
                const int f    = hd >> 1;
#pragma unroll
                for (int h = 0; h < 2; h++) {
                    const int row = r0 + h * 8;
                    float e = cc[h * 2 + 0], o = cc[h * 2 + 1];
                    float re = e, ro = o;
                    if (mode != 3) {
                        const float cth = cosT[row * 32 + f];
                        const float sth = sinT[row * 32 + f];
                        re = e * cth - o * sth;
                        ro = e * sth + o * cth;
                        if (mode == 1) { re *= QSCALE; ro *= QSCALE; }
                    }
                    float* dst = out + ((size_t)head * SEQ + row) * HDIM + hd;
                    dst[0] = __uint_as_float(f2t(re));
                    dst[1] = __uint_as_float(f2t(ro));
                }
            }
        }
    }
}

// ---------------------------------------------------------------------------
// Register-resident TF32 flash attention, M=32 warp tile, cp.async 2-stage.
// CTA = 128 threads (4 warps), 128 queries/CTA.
// K [k][d] stride 68, V [k][d] stride 72 (both raw tf32 bit copies).
// ---------------------------------------------------------------------------
#define FP 68
#define VP 72
#define STAGE_W (64 * FP + 64 * VP)   // words per stage
#define FLASH_SMEM (2 * STAGE_W * (int)sizeof(uint32_t))

__global__ void __launch_bounds__(128, 2) flash_reg(
    const float* __restrict__ Q, const float* __restrict__ K,
    const float* __restrict__ V, float* __restrict__ att)
{
    extern __shared__ uint32_t fsm[];

    const int tid  = threadIdx.x;
    const int lane = tid & 31;
    const int wid  = tid >> 5;
    const int g4   = lane >> 2;
    const int t4   = lane & 3;

    const int qblk = gridDim.x - 1 - blockIdx.x;   // longest first
    const int head = blockIdx.y;

    const uint32_t smemu = (uint32_t)__cvta_generic_to_shared(fsm);
    const float* Kh0 = K + (size_t)head * SEQ * HDIM;
    const float* Vh0 = V + (size_t)head * SEQ * HDIM;

    // prefetch: 8 K-chunks + 8 V-chunks of 16B per thread per tile
    auto prefetch = [&](int buf, int kb) {
        const uint32_t base = smemu + buf * STAGE_W * 4;
        const float* Kh = Kh0 + (size_t)kb * 64 * HDIM;
        const float* Vh = Vh0 + (size_t)kb * 64 * HDIM;
#pragma unroll
        for (int j = 0; j < 8; j++) {
            const int cidx = tid + j * 128;       // 0..1023
            const int r = cidx >> 4, c4 = (cidx & 15) << 2;
            cpa16(base + (r * FP + c4) * 4, Kh + r * HDIM + c4);
            cpa16(base + (64 * FP + r * VP + c4) * 4, Vh + r * HDIM + c4);
        }
    };

    // --- Q fragments (pre-scaled tf32 bits) direct from global ---
    const float* Qh = Q + ((size_t)head * SEQ + qblk * 128) * HDIM;
    uint32_t qf[8][2][4];
#pragma unroll
    for (int kk = 0; kk < 8; kk++)
#pragma unroll
        for (int mh = 0; mh < 2; mh++) {
            const int r = wid * 32 + mh * 16 + g4;
            const int d = kk * 8 + t4;
            qf[kk][mh][0] = __float_as_uint(Qh[(size_t)r * HDIM + d]);
            qf[kk][mh][1] = __float_as_uint(Qh[(size_t)(r + 8) * HDIM + d]);
            qf[kk][mh][2] = __float_as_uint(Qh[(size_t)r * HDIM + d + 4]);
            qf[kk][mh][3] = __float_as_uint(Qh[(size_t)(r + 8) * HDIM + d + 4]);
        }

    float o[2][8][4];
#pragma unroll
    for (int mh = 0; mh < 2; mh++)
#pragma unroll
        for (int nt = 0; nt < 8; nt++)
#pragma unroll
            for (int i = 0; i < 4; i++) o[mh][nt][i] = 0.f;

    float m[2][2], l[2][2];
#pragma unroll
    for (int mh = 0; mh < 2; mh++) {
        m[mh][0] = -INFINITY; m[mh][1] = -INFINITY;
        l[mh][0] = 0.f;       l[mh][1] = 0.f;
    }

    const int srcA = (lane & 28) | (t4 >> 1);
    const int srcB = srcA + 2;
    const bool odd = (t4 & 1);

    const int nkb = 2 * qblk + 2;
    prefetch(0, 0); cpa_commit();
    if (nkb > 1) { prefetch(1, 1); cpa_commit(); }

    for (int kb = 0; kb < nkb; kb++) {
        if (kb + 1 < nkb) cpa_wait<1>(); else cpa_wait<0>();
        __syncthreads();

        const uint32_t* sK = fsm + (kb & 1) * STAGE_W;
        const uint32_t* sV = sK + 64 * FP;

        // ---- S = Q K^T ----
        float sc[2][8][4];
#pragma unroll
        for (int mh = 0; mh < 2; mh++)
#pragma unroll
            for (int nt = 0; nt < 8; nt++)
#pragma unroll
                for (int i = 0; i < 4; i++) sc[mh][nt][i] = 0.f;

        const uint32_t* kbase = sK + g4 * FP + t4;
#pragma unroll
        for (int kk = 0; kk < 8; kk++) {
#pragma unroll
            for (int nt = 0; nt < 8; nt++) {
                const uint32_t* bp = kbase + nt * 8 * FP + kk * 8;
                const uint32_t b0 = bp[0], b1 = bp[4];
                mma8(sc[0][nt], qf[kk][0][0], qf[kk][0][1], qf[kk][0][2], qf[kk][0][3], b0, b1);
                mma8(sc[1][nt], qf[kk][1][0], qf[kk][1][1], qf[kk][1][2], qf[kk][1][3], b0, b1);
            }
        }

        // ---- causal mask ----
        if (kb >= 2 * qblk) {
#pragma unroll
            for (int mh = 0; mh < 2; mh++) {
                const int r0 = qblk * 128 + wid * 32 + mh * 16 + g4;
                const int r1 = r0 + 8;
#pragma unroll
                for (int nt = 0; nt < 8; nt++) {
                    const int col = kb * 64 + nt * 8 + (t4 << 1);
                    if (col > r0)     sc[mh][nt][0] = -INFINITY;
                    if (col + 1 > r0) sc[mh][nt][1] = -INFINITY;
                    if (col > r1)     sc[mh][nt][2] = -INFINITY;
                    if (col + 1 > r1) sc[mh][nt][3] = -INFINITY;
                }
            }
        }

        // ---- online softmax (log2 domain) ----
        float corr[2][2];
#pragma unroll
        for (int mh = 0; mh < 2; mh++) {
            float mx0 = -INFINITY, mx1 = -INFINITY;
#pragma unroll
            for (int nt = 0; nt < 8; nt++) {
                mx0 = fmaxf(mx0, fmaxf(sc[mh][nt][0], sc[mh][nt][1]));
                mx1 = fmaxf(mx1, fmaxf(sc[mh][nt][2], sc[mh][nt][3]));
            }
            mx0 = fmaxf(mx0, __shfl_xor_sync(0xffffffffu, mx0, 1));
            mx0 = fmaxf(mx0, __shfl_xor_sync(0xffffffffu, mx0, 2));
            mx1 = fmaxf(mx1, __shfl_xor_sync(0xffffffffu, mx1, 1));
            mx1 = fmaxf(mx1, __shfl_xor_sync(0xffffffffu, mx1, 2));

            const float mn0 = fmaxf(m[mh][0], mx0);
            const float mn1 = fmaxf(m[mh][1], mx1);
            corr[mh][0] = ex2(m[mh][0] - mn0);
            corr[mh][1] = ex2(m[mh][1] - mn1);
            m[mh][0] = mn0; m[mh][1] = mn1;

            float ls0 = 0.f, ls1 = 0.f;
#pragma unroll
            for (int nt = 0; nt < 8; nt++) {
                sc[mh][nt][0] = ex2(sc[mh][nt][0] - mn0);
                sc[mh][nt][1] = ex2(sc[mh][nt][1] - mn0);
                sc[mh][nt][2] = ex2(sc[mh][nt][2] - mn1);
                sc[mh][nt][3] = ex2(sc[mh][nt][3] - mn1);
                ls0 += sc[mh][nt][0] + sc[mh][nt][1];
                ls1 += sc[mh][nt][2] + sc[mh][nt][3];
            }
            ls0 += __shfl_xor_sync(0xffffffffu, ls0, 1);
            ls0 += __shfl_xor_sync(0xffffffffu, ls0, 2);
            ls1 += __shfl_xor_sync(0xffffffffu, ls1, 1);
            ls1 += __shfl_xor_sync(0xffffffffu, ls1, 2);
            l[mh][0] = l[mh][0] * corr[mh][0] + ls0;
            l[mh][1] = l[mh][1] * corr[mh][1] + ls1;

#pragma unroll
            for (int nt = 0; nt < 8; nt++) {
                o[mh][nt][0] *= corr[mh][0]; o[mh][nt][1] *= corr[mh][0];
                o[mh][nt][2] *= corr[mh][1]; o[mh][nt][3] *= corr[mh][1];
            }
        }

        // ---- O += P V ----
        const uint32_t* vbase = sV + t4 * VP + g4;
#pragma unroll
        for (int kk = 0; kk < 8; kk++) {
            uint32_t pa[2][4];
#pragma unroll
            for (int mh = 0; mh < 2; mh++) {
                const float v0 = __shfl_sync(0xffffffffu, sc[mh][kk][0], srcA);
                const float v1 = __shfl_sync(0xffffffffu, sc[mh][kk][1], srcA);
                const float v2 = __shfl_sync(0xffffffffu, sc[mh][kk][2], srcA);
                const float v3 = __shfl_sync(0xffffffffu, sc[mh][kk][3], srcA);
                const float v4 = __shfl_sync(0xffffffffu, sc[mh][kk][0], srcB);
                const float v5 = __shfl_sync(0xffffffffu, sc[mh][kk][1], srcB);
                const float v6 = __shfl_sync(0xffffffffu, sc[mh][kk][2], srcB);
                const float v7 = __shfl_sync(0xffffffffu, sc[mh][kk][3], srcB);
                pa[mh][0] = f2t(odd ? v1 : v0);
                pa[mh][1] = f2t(odd ? v3 : v2);
                pa[mh][2] = f2t(odd ? v5 : v4);
                pa[mh][3] = f2t(odd ? v7 : v6);
            }
            const uint32_t* vrow = vbase + kk * 8 * VP;
#pragma unroll
            for (int nt = 0; nt < 8; nt++) {
                const uint32_t b0 = vrow[nt * 8];
                const uint32_t b1 = vrow[4 * VP + nt * 8];
                mma8(o[0][nt], pa[0][0], pa[0][1], pa[0][2], pa[0][3], b0, b1);
                mma8(o[1][nt], pa[1][0], pa[1][1], pa[1][2], pa[1][3], b0, b1);
            }
        }

        __syncthreads();
        if (kb + 2 < nkb) { prefetch(kb & 1, kb + 2); cpa_commit(); }
    }

    // ---- epilogue: normalize, store tf32 bits to [s][d] ----
#pragma unroll
    for (int mh = 0; mh < 2; mh++) {
        const float inv0 = 1.f / l[mh][0];
        const float inv1 = 1.f / l[mh][1];
        const int r0 = qblk * 128 + wid * 32 + mh * 16 + g4;
#pragma unroll
        for (int nt = 0; nt < 8; nt++) {
            const int col = head * HDIM + nt * 8 + (t4 << 1);
            *(float2*)(att + (size_t)r0 * DIM + col) = make_float2(
                __uint_as_float(f2t(o[mh][nt][0] * inv0)),
                __uint_as_float(f2t(o[mh][nt][1] * inv0)));
            *(float2*)(att + (size_t)(r0 + 8) * DIM + col) = make_float2(
                __uint_as_float(f2t(o[mh][nt][2] * inv1)),
                __uint_as_float(f2t(o[mh][nt][3] * inv1)));
        }
    }
}

// ---------------------------------------------------------------------------
// Launch
// ---------------------------------------------------------------------------
extern "C" void kernel_launch(void* const* d_in, const int* in_sizes, int n_in,
                              void* d_out, int out_size)
{
    const float* x    = (const float*)d_in[0];
    const float* cosT = (const float*)d_in[1];
    const float* sinT = (const float*)d_in[2];
    const float* wq   = (const float*)d_in[4];
    const float* wk   = (const float*)d_in[5];
    const float* wv   = (const float*)d_in[6];
    const float* wo   = (const float*)d_in[7];
    float* out = (float*)d_out;

    float *qp, *kp, *vp, *ap, *xt, *wqt, *wkt, *wvt, *wot;
    cudaGetSymbolAddress((void**)&qp, g_q);
    cudaGetSymbolAddress((void**)&kp, g_k);
    cudaGetSymbolAddress((void**)&vp, g_v);
    cudaGetSymbolAddress((void**)&ap, g_att);
    cudaGetSymbolAddress((void**)&xt, g_xt);
    cudaGetSymbolAddress((void**)&wqt, g_wq);
    cudaGetSymbolAddress((void**)&wkt, g_wk);
    cudaGetSymbolAddress((void**)&wvt, g_wv);
    cudaGetSymbolAddress((void**)&wot, g_wo);

    cudaFuncSetAttribute(flash_reg,
                         cudaFuncAttributeMaxDynamicSharedMemorySize, FLASH_SMEM);

    // Convert inputs to tf32 bits once
    cvt_tf32<<<512, 256>>>(x, xt, SEQ * DIM / 4);
    cvt_tf32<<<256, 256>>>(wq, wqt, DIM * DIM / 4);
    cvt_tf32<<<256, 256>>>(wk, wkt, DIM * DIM / 4);
    cvt_tf32<<<256, 256>>>(wv, wvt, DIM * DIM / 4);
    cvt_tf32<<<256, 256>>>(wo, wot, DIM * DIM / 4);

    // Fused QKV projections (z = 0,1,2 -> Q,K,V)
    dim3 ggrid(DIM / 128, SEQ / 128, 3);
    gemm_tf32<<<ggrid, 256>>>(xt, wqt, wkt, wvt, qp, kp, vp, cosT, sinT, 1);

    dim3 fgrid(SEQ / 128, NH);
    flash_reg<<<fgrid, 128, FLASH_SMEM>>>(qp, kp, vp, ap);

    // Output projection
    dim3 ogrid(DIM / 128, SEQ / 128, 1);
    gemm_tf32<<<ogrid, 256>>>(ap, wot, wot, wot, out, out, out, cosT, sinT, 0);
}

// round 7
// speedup vs baseline: 4.4642x; 1.1539x over previous
#include <cuda_runtime.h>
#include <math.h>
#include <stdint.h>

#define SEQ 4096
#define DIM 1024
#define NH  16
#define HDIM 64

// Scratch (tf32 bits stored as float)
__device__ float g_q[NH * SEQ * HDIM];   // [h][s][hd] tf32, pre-scaled
__device__ float g_k[NH * SEQ * HDIM];   // [h][s][hd] tf32
__device__ float g_v[NH * SEQ * HDIM];   // [h][s][hd] tf32
__device__ float g_att[SEQ * DIM];       // [s][d]     tf32
__device__ float g_xt[SEQ * DIM];        // x as tf32
__device__ float g_wq[DIM * DIM];        // weights as tf32
__device__ float g_wk[DIM * DIM];
__device__ float g_wv[DIM * DIM];
__device__ float g_wo[DIM * DIM];

#define QSCALE (0.125f * 1.4426950408889634f)   // 1/sqrt(64) * log2(e)

__device__ __forceinline__ uint32_t f2t(float f) {
    uint32_t u;
    asm("cvt.rna.tf32.f32 %0, %1;" : "=r"(u) : "f"(f));
    return u;
}

__device__ __forceinline__ float ex2(float x) {
    float r;
    asm("ex2.approx.f32 %0, %1;" : "=f"(r) : "f"(x));
    return r;
}

__device__ __forceinline__ void mma8(float c[4],
    uint32_t a0, uint32_t a1, uint32_t a2, uint32_t a3,
    uint32_t b0, uint32_t b1)
{
    asm volatile(
        "mma.sync.aligned.m16n8k8.row.col.f32.tf32.tf32.f32 "
        "{%0,%1,%2,%3},{%4,%5,%6,%7},{%8,%9},{%0,%1,%2,%3};"
        : "+f"(c[0]), "+f"(c[1]), "+f"(c[2]), "+f"(c[3])
        : "r"(a0), "r"(a1), "r"(a2), "r"(a3), "r"(b0), "r"(b1));
}

__device__ __forceinline__ void cpa16(uint32_t dst_smem, const void* src) {
    asm volatile("cp.async.cg.shared.global [%0], [%1], 16;"
                 :: "r"(dst_smem), "l"(src));
}
__device__ __forceinline__ void cpa_commit() {
    asm volatile("cp.async.commit_group;");
}
template<int N>
__device__ __forceinline__ void cpa_wait() {
    asm volatile("cp.async.wait_group %0;" :: "n"(N));
}

// ---------------------------------------------------------------------------
// Convert fp32 -> tf32 bits
// ---------------------------------------------------------------------------
__global__ void cvt_tf32(const float* __restrict__ src, float* __restrict__ dst,
                         int n4)
{
    for (int i = blockIdx.x * blockDim.x + threadIdx.x; i < n4;
         i += gridDim.x * blockDim.x) {
        float4 v = ((const float4*)src)[i];
        v.x = __uint_as_float(f2t(v.x));
        v.y = __uint_as_float(f2t(v.y));
        v.z = __uint_as_float(f2t(v.z));
        v.w = __uint_as_float(f2t(v.w));
        ((float4*)dst)[i] = v;
    }
}

// 4 weight matrices in one launch (blockIdx.z selects)
__global__ void cvt_tf32_w(const float* __restrict__ s0, float* __restrict__ d0,
                           const float* __restrict__ s1, float* __restrict__ d1,
                           const float* __restrict__ s2, float* __restrict__ d2,
                           const float* __restrict__ s3, float* __restrict__ d3,
                           int n4)
{
    const float* src; float* dst;
    if (blockIdx.z == 0)      { src = s0; dst = d0; }
    else if (blockIdx.z == 1) { src = s1; dst = d1; }
    else if (blockIdx.z == 2) { src = s2; dst = d2; }
    else                      { src = s3; dst = d3; }
    for (int i = blockIdx.x * blockDim.x + threadIdx.x; i < n4;
         i += gridDim.x * blockDim.x) {
        float4 v = ((const float4*)src)[i];
        v.x = __uint_as_float(f2t(v.x));
        v.y = __uint_as_float(f2t(v.y));
        v.z = __uint_as_float(f2t(v.z));
        v.w = __uint_as_float(f2t(v.w));
        ((float4*)dst)[i] = v;
    }
}

// ---------------------------------------------------------------------------
// TF32 GEMM (mma.sync), BK=32, 3-stage cp.async, ONE barrier per chunk.
// C[4096,1024] = A[M,K] * W[N,K]^T ; 128x128 tile, 8 warps (4x2), 32x64/warp.
// mode 0: plain f32 out; 1: RoPE+QSCALE->tf32 [h][s][hd];
// 2: RoPE->tf32 [h][s][hd]; 3: tf32 [h][s][hd]
// ---------------------------------------------------------------------------
#define GBK   32
#define GSAS  36                               // padded stride (words)
#define GSTW  (128 * GSAS)                     // words per operand per stage
#define GSTB  (2 * GSTW * 4)                   // stage bytes (A + B)
#define GSMEM (3 * GSTB)                       // 110592 bytes

__global__ void __launch_bounds__(256) gemm_tf32(
    const float* __restrict__ A,
    const float* __restrict__ W0, const float* __restrict__ W1,
    const float* __restrict__ W2,
    float* __restrict__ out0, float* __restrict__ out1,
    float* __restrict__ out2,
    const float* __restrict__ cosT, const float* __restrict__ sinT,
    int mode0)
{
    extern __shared__ uint32_t gsm[];

    const float* W; float* out; int mode;
    if (blockIdx.z == 0)      { W = W0; out = out0; mode = mode0; }
    else if (blockIdx.z == 1) { W = W1; out = out1; mode = 2; }
    else                      { W = W2; out = out2; mode = 3; }

    const int tid  = threadIdx.x;
    const int lane = tid & 31;
    const int wid  = tid >> 5;
    const int wm   = wid >> 1;      // 0..3
    const int wn   = wid & 1;       // 0..1
    const int g4   = lane >> 2;
    const int t4   = lane & 3;

    const int mBase = blockIdx.y * 128;
    const int nBase = blockIdx.x * 128;

    const uint32_t smemu = (uint32_t)__cvta_generic_to_shared(gsm);

    // prefetch one 32-wide K chunk of A and W into stage s
    auto prefetch = [&](int s, int t) {
        const int koff = t * GBK;
        const uint32_t abase = smemu + s * GSTB;
        const uint32_t bbase = abase + GSTW * 4;
#pragma unroll
        for (int j = 0; j < 4; j++) {
            const int idx = tid + j * 256;       // 0..1023
            const int r = idx >> 3, c4 = (idx & 7) << 2;
            cpa16(abase + (r * GSAS + c4) * 4, A + (size_t)(mBase + r) * DIM + koff + c4);
            cpa16(bbase + (r * GSAS + c4) * 4, W + (size_t)(nBase + r) * DIM + koff + c4);
        }
    };

    float c[2][8][4];
#pragma unroll
    for (int mt = 0; mt < 2; mt++)
#pragma unroll
        for (int nt = 0; nt < 8; nt++)
#pragma unroll
            for (int i = 0; i < 4; i++) c[mt][nt][i] = 0.f;

    const int NT = DIM / GBK;   // 32
    prefetch(0, 0); cpa_commit();
    prefetch(1, 1); cpa_commit();

    for (int t = 0; t < NT; t++) {
        if (t + 1 < NT) cpa_wait<1>(); else cpa_wait<0>();
        __syncthreads();   // all warps: chunk t data visible; compute(t-1) done

        // prefetch t+2 into stage (t+2)%3 == (t-1)%3 (drained by barrier above)
        if (t + 2 < NT) { prefetch((t + 2) % 3, t + 2); cpa_commit(); }

        const uint32_t* a_s = gsm + (t % 3) * (GSTB / 4);
        const uint32_t* b_s = a_s + GSTW;
#pragma unroll
        for (int ks = 0; ks < 4; ks++) {
            const int kk = ks * 8 + t4;
            uint32_t af[2][4], bf[8][2];
#pragma unroll
            for (int mt = 0; mt < 2; mt++) {
                const int r = wm * 32 + mt * 16 + g4;
                af[mt][0] = a_s[r * GSAS + kk];
                af[mt][1] = a_s[(r + 8) * GSAS + kk];
                af[mt][2] = a_s[r * GSAS + kk + 4];
                af[mt][3] = a_s[(r + 8) * GSAS + kk + 4];
            }
#pragma unroll
            for (int nt = 0; nt < 8; nt++) {
                const int r = wn * 64 + nt * 8 + g4;
                bf[nt][0] = b_s[r * GSAS + kk];
                bf[nt][1] = b_s[r * GSAS + kk + 4];
            }
#pragma unroll
            for (int mt = 0; mt < 2; mt++)
#pragma unroll
                for (int nt = 0; nt < 8; nt++)
                    mma8(c[mt][nt], af[mt][0], af[mt][1], af[mt][2], af[mt][3],
                         bf[nt][0], bf[nt][1]);
        }
    }

    // Epilogue
#pragma unroll
    for (int mt = 0; mt < 2; mt++) {
        const int r0 = mBase + wm * 32 + mt * 16 + g4;
#pragma unroll
        for (int nt = 0; nt < 8; nt++) {
            const int colg = nBase + wn * 64 + nt * 8 + (t4 << 1);
            const float* cc = c[mt][nt];
            if (mode == 0) {
                *(float2*)(out + (size_t)r0 * DIM + colg)       = make_float2(cc[0], cc[1]);
                *(float2*)(out + (size_t)(r0 + 8) * DIM + colg) = make_float2(cc[2], cc[3]);
            } else {
                const int head = colg >> 6;
                const int hd   = colg & 63;
                const int f    = hd >> 1;
#pragma unroll
                for (int h = 0; h < 2; h++) {
                    const int row = r0 + h * 8;
                    float e = cc[h * 2 + 0], o = cc[h * 2 + 1];
                    float re = e, ro = o;
                    if (mode != 3) {
                        const float cth = cosT[row * 32 + f];
                        const float sth = sinT[row * 32 + f];
                        re = e * cth - o * sth;
                        ro = e * sth + o * cth;
                        if (mode == 1) { re *= QSCALE; ro *= QSCALE; }
                    }
                    float* dst = out + ((size_t)head * SEQ + row) * HDIM + hd;
                    dst[0] = __uint_as_float(f2t(re));
                    dst[1] = __uint_as_float(f2t(ro));
                }
            }
        }
    }
}

// ---------------------------------------------------------------------------
// Register-resident TF32 flash attention, M=32 warp tile, cp.async 2-stage.
// (unchanged from R5 — proven at ~320us)
// ---------------------------------------------------------------------------
#define FP 68
#define VP 72
#define STAGE_W (64 * FP + 64 * VP)
#define FLASH_SMEM (2 * STAGE_W * (int)sizeof(uint32_t))

__global__ void __launch_bounds__(128, 2) flash_reg(
    const float* __restrict__ Q, const float* __restrict__ K,
    const float* __restrict__ V, float* __restrict__ att)
{
    extern __shared__ uint32_t fsm[];

    const int tid  = threadIdx.x;
    const int lane = tid & 31;
    const int wid  = tid >> 5;
    const int g4   = lane >> 2;
    const int t4   = lane & 3;

    const int qblk = gridDim.x - 1 - blockIdx.x;
    const int head = blockIdx.y;

    const uint32_t smemu = (uint32_t)__cvta_generic_to_shared(fsm);
    const float* Kh0 = K + (size_t)head * SEQ * HDIM;
    const float* Vh0 = V + (size_t)head * SEQ * HDIM;

    auto prefetch = [&](int buf, int kb) {
        const uint32_t base = smemu + buf * STAGE_W * 4;
        const float* Kh = Kh0 + (size_t)kb * 64 * HDIM;
        const float* Vh = Vh0 + (size_t)kb * 64 * HDIM;
#pragma unroll
        for (int j = 0; j < 8; j++) {
            const int cidx = tid + j * 128;
            const int r = cidx >> 4, c4 = (cidx & 15) << 2;
            cpa16(base + (r * FP + c4) * 4, Kh + r * HDIM + c4);
            cpa16(base + (64 * FP + r * VP + c4) * 4, Vh + r * HDIM + c4);
        }
    };

    const float* Qh = Q + ((size_t)head * SEQ + qblk * 128) * HDIM;
    uint32_t qf[8][2][4];
#pragma unroll
    for (int kk = 0; kk < 8; kk++)
#pragma unroll
        for (int mh = 0; mh < 2; mh++) {
            const int r = wid * 32 + mh * 16 + g4;
            const int d = kk * 8 + t4;
            qf[kk][mh][0] = __float_as_uint(Qh[(size_t)r * HDIM + d]);
            qf[kk][mh][1] = __float_as_uint(Qh[(size_t)(r + 8) * HDIM + d]);
            qf[kk][mh][2] = __float_as_uint(Qh[(size_t)r * HDIM + d + 4]);
            qf[kk][mh][3] = __float_as_uint(Qh[(size_t)(r + 8) * HDIM + d + 4]);
        }

    float o[2][8][4];
#pragma unroll
    for (int mh = 0; mh < 2; mh++)
#pragma unroll
        for (int nt = 0; nt < 8; nt++)
#pragma unroll
            for (int i = 0; i < 4; i++) o[mh][nt][i] = 0.f;

    float m[2][2], l[2][2];
#pragma unroll
    for (int mh = 0; mh < 2; mh++) {
        m[mh][0] = -INFINITY; m[mh][1] = -INFINITY;
        l[mh][0] = 0.f;       l[mh][1] = 0.f;
    }

    const int srcA = (lane & 28) | (t4 >> 1);
    const int srcB = srcA + 2;
    const bool odd = (t4 & 1);

    const int nkb = 2 * qblk + 2;
    prefetch(0, 0); cpa_commit();
    if (nkb > 1) { prefetch(1, 1); cpa_commit(); }

    for (int kb = 0; kb < nkb; kb++) {
        if (kb + 1 < nkb) cpa_wait<1>(); else cpa_wait<0>();
        __syncthreads();

        const uint32_t* sK = fsm + (kb & 1) * STAGE_W;
        const uint32_t* sV = sK + 64 * FP;

        float sc[2][8][4];
#pragma unroll
        for (int mh = 0; mh < 2; mh++)
#pragma unroll
            for (int nt = 0; nt < 8; nt++)
#pragma unroll
                for (int i = 0; i < 4; i++) sc[mh][nt][i] = 0.f;

        const uint32_t* kbase = sK + g4 * FP + t4;
#pragma unroll
        for (int kk = 0; kk < 8; kk++) {
#pragma unroll
            for (int nt = 0; nt < 8; nt++) {
                const uint32_t* bp = kbase + nt * 8 * FP + kk * 8;
                const uint32_t b0 = bp[0], b1 = bp[4];
                mma8(sc[0][nt], qf[kk][0][0], qf[kk][0][1], qf[kk][0][2], qf[kk][0][3], b0, b1);
                mma8(sc[1][nt], qf[kk][1][0], qf[kk][1][1], qf[kk][1][2], qf[kk][1][3], b0, b1);
            }
        }

        if (kb >= 2 * qblk) {
#pragma unroll
            for (int mh = 0; mh < 2; mh++) {
                const int r0 = qblk * 128 + wid * 32 + mh * 16 + g4;
                const int r1 = r0 + 8;
#pragma unroll
                for (int nt = 0; nt < 8; nt++) {
                    const int col = kb * 64 + nt * 8 + (t4 << 1);
                    if (col > r0)     sc[mh][nt][0] = -INFINITY;
                    if (col + 1 > r0) sc[mh][nt][1] = -INFINITY;
                    if (col > r1)     sc[mh][nt][2] = -INFINITY;
                    if (col + 1 > r1) sc[mh][nt][3] = -INFINITY;
                }
            }
        }

        float corr[2][2];
#pragma unroll
        for (int mh = 0; mh < 2; mh++) {
            float mx0 = -INFINITY, mx1 = -INFINITY;
#pragma unroll
            for (int nt = 0; nt < 8; nt++) {
                mx0 = fmaxf(mx0, fmaxf(sc[mh][nt][0], sc[mh][nt][1]));
                mx1 = fmaxf(mx1, fmaxf(sc[mh][nt][2], sc[mh][nt][3]));
            }
            mx0 = fmaxf(mx0, __shfl_xor_sync(0xffffffffu, mx0, 1));
            mx0 = fmaxf(mx0, __shfl_xor_sync(0xffffffffu, mx0, 2));
            mx1 = fmaxf(mx1, __shfl_xor_sync(0xffffffffu, mx1, 1));
            mx1 = fmaxf(mx1, __shfl_xor_sync(0xffffffffu, mx1, 2));

            const float mn0 = fmaxf(m[mh][0], mx0);
            const float mn1 = fmaxf(m[mh][1], mx1);
            corr[mh][0] = ex2(m[mh][0] - mn0);
            corr[mh][1] = ex2(m[mh][1] - mn1);
            m[mh][0] = mn0; m[mh][1] = mn1;

            float ls0 = 0.f, ls1 = 0.f;
#pragma unroll
            for (int nt = 0; nt < 8; nt++) {
                sc[mh][nt][0] = ex2(sc[mh][nt][0] - mn0);
                sc[mh][nt][1] = ex2(sc[mh][nt][1] - mn0);
                sc[mh][nt][2] = ex2(sc[mh][nt][2] - mn1);
                sc[mh][nt][3] = ex2(sc[mh][nt][3] - mn1);
                ls0 += sc[mh][nt][0] + sc[mh][nt][1];
                ls1 += sc[mh][nt][2] + sc[mh][nt][3];
            }
            ls0 += __shfl_xor_sync(0xffffffffu, ls0, 1);
            ls0 += __shfl_xor_sync(0xffffffffu, ls0, 2);
            ls1 += __shfl_xor_sync(0xffffffffu, ls1, 1);
            ls1 += __shfl_xor_sync(0xffffffffu, ls1, 2);
            l[mh][0] = l[mh][0] * corr[mh][0] + ls0;
            l[mh][1] = l[mh][1] * corr[mh][1] + ls1;

#pragma unroll
            for (int nt = 0; nt < 8; nt++) {
                o[mh][nt][0] *= corr[mh][0]; o[mh][nt][1] *= corr[mh][0];
                o[mh][nt][2] *= corr[mh][1]; o[mh][nt][3] *= corr[mh][1];
            }
        }

        const uint32_t* vbase = sV + t4 * VP + g4;
#pragma unroll
        for (int kk = 0; kk < 8; kk++) {
            uint32_t pa[2][4];
#pragma unroll
            for (int mh = 0; mh < 2; mh++) {
                const float v0 = __shfl_sync(0xffffffffu, sc[mh][kk][0], srcA);
                const float v1 = __shfl_sync(0xffffffffu, sc[mh][kk][1], srcA);
                const float v2 = __shfl_sync(0xffffffffu, sc[mh][kk][2], srcA);
                const float v3 = __shfl_sync(0xffffffffu, sc[mh][kk][3], srcA);
                const float v4 = __shfl_sync(0xffffffffu, sc[mh][kk][0], srcB);
                const float v5 = __shfl_sync(0xffffffffu, sc[mh][kk][1], srcB);
                const float v6 = __shfl_sync(0xffffffffu, sc[mh][kk][2], srcB);
                const float v7 = __shfl_sync(0xffffffffu, sc[mh][kk][3], srcB);
                pa[mh][0] = f2t(odd ? v1 : v0);
                pa[mh][1] = f2t(odd ? v3 : v2);
                pa[mh][2] = f2t(odd ? v5 : v4);
                pa[mh][3] = f2t(odd ? v7 : v6);
            }
            const uint32_t* vrow = vbase + kk * 8 * VP;
#pragma unroll
            for (int nt = 0; nt < 8; nt++) {
                const uint32_t b0 = vrow[nt * 8];
                const uint32_t b1 = vrow[4 * VP + nt * 8];
                mma8(o[0][nt], pa[0][0], pa[0][1], pa[0][2], pa[0][3], b0, b1);
                mma8(o[1][nt], pa[1][0], pa[1][1], pa[1][2], pa[1][3], b0, b1);
            }
        }

        __syncthreads();
        if (kb + 2 < nkb) { prefetch(kb & 1, kb + 2); cpa_commit(); }
    }

#pragma unroll
    for (int mh = 0; mh < 2; mh++) {
        const float inv0 = 1.f / l[mh][0];
        const float inv1 = 1.f / l[mh][1];
        const int r0 = qblk * 128 + wid * 32 + mh * 16 + g4;
#pragma unroll
        for (int nt = 0; nt < 8; nt++) {
            const int col = head * HDIM + nt * 8 + (t4 << 1);
            *(float2*)(att + (size_t)r0 * DIM + col) = make_float2(
                __uint_as_float(f2t(o[mh][nt][0] * inv0)),
                __uint_as_float(f2t(o[mh][nt][1] * inv0)));
            *(float2*)(att + (size_t)(r0 + 8) * DIM + col) = make_float2(
                __uint_as_float(f2t(o[mh][nt][2] * inv1)),
                __uint_as_float(f2t(o[mh][nt][3] * inv1)));
        }
    }
}

// ---------------------------------------------------------------------------
// Launch
// ---------------------------------------------------------------------------
extern "C" void kernel_launch(void* const* d_in, const int* in_sizes, int n_in,
                              void* d_out, int out_size)
{
    const float* x    = (const float*)d_in[0];
    const float* cosT = (const float*)d_in[1];
    const float* sinT = (const float*)d_in[2];
    const float* wq   = (const float*)d_in[4];
    const float* wk   = (const float*)d_in[5];
    const float* wv   = (const float*)d_in[6];
    const float* wo   = (const float*)d_in[7];
    float* out = (float*)d_out;

    float *qp, *kp, *vp, *ap, *xt, *wqt, *wkt, *wvt, *wot;
    cudaGetSymbolAddress((void**)&qp, g_q);
    cudaGetSymbolAddress((void**)&kp, g_k);
    cudaGetSymbolAddress((void**)&vp, g_v);
    cudaGetSymbolAddress((void**)&ap, g_att);
    cudaGetSymbolAddress((void**)&xt, g_xt);
    cudaGetSymbolAddress((void**)&wqt, g_wq);
    cudaGetSymbolAddress((void**)&wkt, g_wk);
    cudaGetSymbolAddress((void**)&wvt, g_wv);
    cudaGetSymbolAddress((void**)&wot, g_wo);

    cudaFuncSetAttribute(flash_reg,
                         cudaFuncAttributeMaxDynamicSharedMemorySize, FLASH_SMEM);
    cudaFuncSetAttribute(gemm_tf32,
                         cudaFuncAttributeMaxDynamicSharedMemorySize, GSMEM);

    // Convert inputs to tf32 bits once
    cvt_tf32<<<512, 256>>>(x, xt, SEQ * DIM / 4);
    dim3 wgrid(128, 1, 4);
    cvt_tf32_w<<<wgrid, 256>>>(wq, wqt, wk, wkt, wv, wvt, wo, wot, DIM * DIM / 4);

    // Fused QKV projections (z = 0,1,2 -> Q,K,V)
    dim3 ggrid(DIM / 128, SEQ / 128, 3);
    gemm_tf32<<<ggrid, 256, GSMEM>>>(xt, wqt, wkt, wvt, qp, kp, vp, cosT, sinT, 1);

    dim3 fgrid(SEQ / 128, NH);
    flash_reg<<<fgrid, 128, FLASH_SMEM>>>(qp, kp, vp, ap);

    // Output projection
    dim3 ogrid(DIM / 128, SEQ / 128, 1);
    gemm_tf32<<<ogrid, 256, GSMEM>>>(ap, wot, wot, wot, out, out, out, cosT, sinT, 0);
}

// round 8
// speedup vs baseline: 5.0626x; 1.1340x over previous
#include <cuda_runtime.h>
#include <math.h>
#include <stdint.h>

#define SEQ 4096
#define DIM 1024
#define NH  16
#define HDIM 64

// Scratch (tf32 bits stored as float)
__device__ float g_q[NH * SEQ * HDIM];   // [h][s][hd] tf32, pre-scaled
__device__ float g_k[NH * SEQ * HDIM];   // [h][s][hd] tf32
__device__ float g_v[NH * SEQ * HDIM];   // [h][s][hd] tf32
__device__ float g_att[SEQ * DIM];       // [s][d]     tf32
__device__ float g_xt[SEQ * DIM];        // x as tf32
__device__ float g_wq[DIM * DIM];        // weights as tf32
__device__ float g_wk[DIM * DIM];
__device__ float g_wv[DIM * DIM];
__device__ float g_wo[DIM * DIM];

#define QSCALE (0.125f * 1.4426950408889634f)   // 1/sqrt(64) * log2(e)

__device__ __forceinline__ uint32_t f2t(float f) {
    uint32_t u;
    asm("cvt.rna.tf32.f32 %0, %1;" : "=r"(u) : "f"(f));
    return u;
}

__device__ __forceinline__ float ex2(float x) {
    float r;
    asm("ex2.approx.f32 %0, %1;" : "=f"(r) : "f"(x));
    return r;
}

__device__ __forceinline__ void mma8(float c[4],
    uint32_t a0, uint32_t a1, uint32_t a2, uint32_t a3,
    uint32_t b0, uint32_t b1)
{
    asm volatile(
        "mma.sync.aligned.m16n8k8.row.col.f32.tf32.tf32.f32 "
        "{%0,%1,%2,%3},{%4,%5,%6,%7},{%8,%9},{%0,%1,%2,%3};"
        : "+f"(c[0]), "+f"(c[1]), "+f"(c[2]), "+f"(c[3])
        : "r"(a0), "r"(a1), "r"(a2), "r"(a3), "r"(b0), "r"(b1));
}

__device__ __forceinline__ void cpa16(uint32_t dst_smem, const void* src) {
    asm volatile("cp.async.cg.shared.global [%0], [%1], 16;"
                 :: "r"(dst_smem), "l"(src));
}
__device__ __forceinline__ void cpa_commit() {
    asm volatile("cp.async.commit_group;");
}
template<int N>
__device__ __forceinline__ void cpa_wait() {
    asm volatile("cp.async.wait_group %0;" :: "n"(N));
}

// ---------------------------------------------------------------------------
// Convert fp32 -> tf32 bits
// ---------------------------------------------------------------------------
__global__ void cvt_tf32(const float* __restrict__ src, float* __restrict__ dst,
                         int n4)
{
    for (int i = blockIdx.x * blockDim.x + threadIdx.x; i < n4;
         i += gridDim.x * blockDim.x) {
        float4 v = ((const float4*)src)[i];
        v.x = __uint_as_float(f2t(v.x));
        v.y = __uint_as_float(f2t(v.y));
        v.z = __uint_as_float(f2t(v.z));
        v.w = __uint_as_float(f2t(v.w));
        ((float4*)dst)[i] = v;
    }
}

__global__ void cvt_tf32_w(const float* __restrict__ s0, float* __restrict__ d0,
                           const float* __restrict__ s1, float* __restrict__ d1,
                           const float* __restrict__ s2, float* __restrict__ d2,
                           const float* __restrict__ s3, float* __restrict__ d3,
                           int n4)
{
    const float* src; float* dst;
    if (blockIdx.z == 0)      { src = s0; dst = d0; }
    else if (blockIdx.z == 1) { src = s1; dst = d1; }
    else if (blockIdx.z == 2) { src = s2; dst = d2; }
    else                      { src = s3; dst = d3; }
    for (int i = blockIdx.x * blockDim.x + threadIdx.x; i < n4;
         i += gridDim.x * blockDim.x) {
        float4 v = ((const float4*)src)[i];
        v.x = __uint_as_float(f2t(v.x));
        v.y = __uint_as_float(f2t(v.y));
        v.z = __uint_as_float(f2t(v.z));
        v.w = __uint_as_float(f2t(v.w));
        ((float4*)dst)[i] = v;
    }
}

// ---------------------------------------------------------------------------
// TF32 GEMM (mma.sync), BK=32, 3-stage cp.async, ONE barrier per chunk.
// (unchanged from R7)
// ---------------------------------------------------------------------------
#define GBK   32
#define GSAS  36
#define GSTW  (128 * GSAS)
#define GSTB  (2 * GSTW * 4)
#define GSMEM (3 * GSTB)

__global__ void __launch_bounds__(256) gemm_tf32(
    const float* __restrict__ A,
    const float* __restrict__ W0, const float* __restrict__ W1,
    const float* __restrict__ W2,
    float* __restrict__ out0, float* __restrict__ out1,
    float* __restrict__ out2,
    const float* __restrict__ cosT, const float* __restrict__ sinT,
    int mode0)
{
    extern __shared__ uint32_t gsm[];

    const float* W; float* out; int mode;
    if (blockIdx.z == 0)      { W = W0; out = out0; mode = mode0; }
    else if (blockIdx.z == 1) { W = W1; out = out1; mode = 2; }
    else                      { W = W2; out = out2; mode = 3; }

    const int tid  = threadIdx.x;
    const int lane = tid & 31;
    const int wid  = tid >> 5;
    const int wm   = wid >> 1;
    const int wn   = wid & 1;
    const int g4   = lane >> 2;
    const int t4   = lane & 3;

    const int mBase = blockIdx.y * 128;
    const int nBase = blockIdx.x * 128;

    const uint32_t smemu = (uint32_t)__cvta_generic_to_shared(gsm);

    auto prefetch = [&](int s, int t) {
        const int koff = t * GBK;
        const uint32_t abase = smemu + s * GSTB;
        const uint32_t bbase = abase + GSTW * 4;
#pragma unroll
        for (int j = 0; j < 4; j++) {
            const int idx = tid + j * 256;
            const int r = idx >> 3, c4 = (idx & 7) << 2;
            cpa16(abase + (r * GSAS + c4) * 4, A + (size_t)(mBase + r) * DIM + koff + c4);
            cpa16(bbase + (r * GSAS + c4) * 4, W + (size_t)(nBase + r) * DIM + koff + c4);
        }
    };

    float c[2][8][4];
#pragma unroll
    for (int mt = 0; mt < 2; mt++)
#pragma unroll
        for (int nt = 0; nt < 8; nt++)
#pragma unroll
            for (int i = 0; i < 4; i++) c[mt][nt][i] = 0.f;

    const int NT = DIM / GBK;
    prefetch(0, 0); cpa_commit();
    prefetch(1, 1); cpa_commit();

    for (int t = 0; t < NT; t++) {
        if (t + 1 < NT) cpa_wait<1>(); else cpa_wait<0>();
        __syncthreads();

        if (t + 2 < NT) { prefetch((t + 2) % 3, t + 2); cpa_commit(); }

        const uint32_t* a_s = gsm + (t % 3) * (GSTB / 4);
        const uint32_t* b_s = a_s + GSTW;
#pragma unroll
        for (int ks = 0; ks < 4; ks++) {
            const int kk = ks * 8 + t4;
            uint32_t af[2][4], bf[8][2];
#pragma unroll
            for (int mt = 0; mt < 2; mt++) {
                const int r = wm * 32 + mt * 16 + g4;
                af[mt][0] = a_s[r * GSAS + kk];
                af[mt][1] = a_s[(r + 8) * GSAS + kk];
                af[mt][2] = a_s[r * GSAS + kk + 4];
                af[mt][3] = a_s[(r + 8) * GSAS + kk + 4];
            }
#pragma unroll
            for (int nt = 0; nt < 8; nt++) {
                const int r = wn * 64 + nt * 8 + g4;
                bf[nt][0] = b_s[r * GSAS + kk];
                bf[nt][1] = b_s[r * GSAS + kk + 4];
            }
#pragma unroll
            for (int mt = 0; mt < 2; mt++)
#pragma unroll
                for (int nt = 0; nt < 8; nt++)
                    mma8(c[mt][nt], af[mt][0], af[mt][1], af[mt][2], af[mt][3],
                         bf[nt][0], bf[nt][1]);
        }
    }

#pragma unroll
    for (int mt = 0; mt < 2; mt++) {
        const int r0 = mBase + wm * 32 + mt * 16 + g4;
#pragma unroll
        for (int nt = 0; nt < 8; nt++) {
            const int colg = nBase + wn * 64 + nt * 8 + (t4 << 1);
            const float* cc = c[mt][nt];
            if (mode == 0) {
                *(float2*)(out + (size_t)r0 * DIM + colg)       = make_float2(cc[0], cc[1]);
                *(float2*)(out + (size_t)(r0 + 8) * DIM + colg) = make_float2(cc[2], cc[3]);
            } else {
                const int head = colg >> 6;
                const int hd   = colg & 63;
                const int f    = hd >> 1;
#pragma unroll
                for (int h = 0; h < 2; h++) {
                    const int row = r0 + h * 8;
                    float e = cc[h * 2 + 0], o = cc[h * 2 + 1];
                    float re = e, ro = o;
                    if (mode != 3) {
                        const float cth = cosT[row * 32 + f];
                        const float sth = sinT[row * 32 + f];
                        re = e * cth - o * sth;
                        ro = e * sth + o * cth;
                        if (mode == 1) { re *= QSCALE; ro *= QSCALE; }
                    }
                    float* dst = out + ((size_t)head * SEQ + row) * HDIM + hd;
                    dst[0] = __uint_as_float(f2t(re));
                    dst[1] = __uint_as_float(f2t(ro));
                }
            }
        }
    }
}

// ---------------------------------------------------------------------------
// TF32 flash attention, M=32 warp tile, 32-key tiles, Q in smem.
// CTA = 128 threads (4 warps), 128 queries/CTA, 3 CTAs/SM target.
// smem: sQ[128][68] persistent + 2 stages of (K[32][68] + V[32][72]).
// ---------------------------------------------------------------------------
#define FPQ 68
#define FP  68
#define VP  72
#define KT  32
#define SQ_W   (128 * FPQ)                  // 8704 words
#define STAGE_W (KT * FP + KT * VP)         // 4480 words
#define FLASH_SMEM ((SQ_W + 2 * STAGE_W) * (int)sizeof(uint32_t))   // 70656 B

__global__ void __launch_bounds__(128, 3) flash_reg(
    const float* __restrict__ Q, const float* __restrict__ K,
    const float* __restrict__ V, float* __restrict__ att)
{
    extern __shared__ uint32_t fsm[];
    uint32_t* sQ = fsm;

    const int tid  = threadIdx.x;
    const int lane = tid & 31;
    const int wid  = tid >> 5;
    const int g4   = lane >> 2;
    const int t4   = lane & 3;

    const int qblk = gridDim.x - 1 - blockIdx.x;   // longest first
    const int head = blockIdx.y;

    const uint32_t smemu = (uint32_t)__cvta_generic_to_shared(fsm);
    const float* Kh0 = K + (size_t)head * SEQ * HDIM;
    const float* Vh0 = V + (size_t)head * SEQ * HDIM;

    // ---- async-load Q tile (128 x 64) into sQ, stride FPQ ----
    {
        const float* Qh = Q + ((size_t)head * SEQ + qblk * 128) * HDIM;
#pragma unroll
        for (int j = 0; j < 16; j++) {
            const int idx = tid + j * 128;       // 0..2047
            const int r = idx >> 4, c4 = (idx & 15) << 2;
            cpa16(smemu + (r * FPQ + c4) * 4, Qh + r * HDIM + c4);
        }
        cpa_commit();
    }

    // prefetch one 32-key tile (K + V) into stage buf
    auto prefetch = [&](int buf, int kb) {
        const uint32_t base = smemu + (SQ_W + buf * STAGE_W) * 4;
        const float* Kh = Kh0 + (size_t)kb * KT * HDIM;
        const float* Vh = Vh0 + (size_t)kb * KT * HDIM;
#pragma unroll
        for (int j = 0; j < 4; j++) {
            const int idx = tid + j * 128;       // 0..511
            const int r = idx >> 4, c4 = (idx & 15) << 2;
            cpa16(base + (r * FP + c4) * 4, Kh + r * HDIM + c4);
            cpa16(base + (KT * FP + r * VP + c4) * 4, Vh + r * HDIM + c4);
        }
    };

    float o[2][8][4];
#pragma unroll
    for (int mh = 0; mh < 2; mh++)
#pragma unroll
        for (int nt = 0; nt < 8; nt++)
#pragma unroll
            for (int i = 0; i < 4; i++) o[mh][nt][i] = 0.f;

    float m[2][2], l[2][2];
#pragma unroll
    for (int mh = 0; mh < 2; mh++) {
        m[mh][0] = -INFINITY; m[mh][1] = -INFINITY;
        l[mh][0] = 0.f;       l[mh][1] = 0.f;
    }

    const int srcA = (lane & 28) | (t4 >> 1);
    const int srcB = srcA + 2;
    const bool odd = (t4 & 1);

    const int nkb = 4 * qblk + 4;   // 32-key tiles
    prefetch(0, 0); cpa_commit();
    prefetch(1, 1); cpa_commit();

    const uint32_t* qbase = sQ + (wid * 32 + g4) * FPQ + t4;

    for (int kb = 0; kb < nkb; kb++) {
        if (kb + 1 < nkb) cpa_wait<1>(); else cpa_wait<0>();
        __syncthreads();

        const uint32_t* sK = fsm + SQ_W + (kb & 1) * STAGE_W;
        const uint32_t* sV = sK + KT * FP;

        // ---- S = Q K^T (Q fragments from smem) ----
        float sc[2][4][4];
#pragma unroll
        for (int mh = 0; mh < 2; mh++)
#pragma unroll
            for (int nt = 0; nt < 4; nt++)
#pragma unroll
                for (int i = 0; i < 4; i++) sc[mh][nt][i] = 0.f;

        const uint32_t* kbase = sK + g4 * FP + t4;
#pragma unroll
        for (int kk = 0; kk < 8; kk++) {
            uint32_t qa[2][4];
#pragma unroll
            for (int mh = 0; mh < 2; mh++) {
                const uint32_t* qp_ = qbase + mh * 16 * FPQ + kk * 8;
                qa[mh][0] = qp_[0];
                qa[mh][1] = qp_[8 * FPQ];
                qa[mh][2] = qp_[4];
                qa[mh][3] = qp_[8 * FPQ + 4];
            }
#pragma unroll
            for (int nt = 0; nt < 4; nt++) {
                const uint32_t* bp = kbase + nt * 8 * FP + kk * 8;
                const uint32_t b0 = bp[0], b1 = bp[4];
                mma8(sc[0][nt], qa[0][0], qa[0][1], qa[0][2], qa[0][3], b0, b1);
                mma8(sc[1][nt], qa[1][0], qa[1][1], qa[1][2], qa[1][3], b0, b1);
            }
        }

        // ---- causal mask (diagonal tiles only) ----
        if (kb >= 4 * qblk) {
#pragma unroll
            for (int mh = 0; mh < 2; mh++) {
                const int r0 = qblk * 128 + wid * 32 + mh * 16 + g4;
                const int r1 = r0 + 8;
#pragma unroll
                for (int nt = 0; nt < 4; nt++) {
                    const int col = kb * KT + nt * 8 + (t4 << 1);
                    if (col > r0)     sc[mh][nt][0] = -INFINITY;
                    if (col + 1 > r0) sc[mh][nt][1] = -INFINITY;
                    if (col > r1)     sc[mh][nt][2] = -INFINITY;
                    if (col + 1 > r1) sc[mh][nt][3] = -INFINITY;
                }
            }
        }

        // ---- online softmax (log2 domain) ----
        float corr[2][2];
#pragma unroll
        for (int mh = 0; mh < 2; mh++) {
            float mx0 = -INFINITY, mx1 = -INFINITY;
#pragma unroll
            for (int nt = 0; nt < 4; nt++) {
                mx0 = fmaxf(mx0, fmaxf(sc[mh][nt][0], sc[mh][nt][1]));
                mx1 = fmaxf(mx1, fmaxf(sc[mh][nt][2], sc[mh][nt][3]));
            }
            mx0 = fmaxf(mx0, __shfl_xor_sync(0xffffffffu, mx0, 1));
            mx0 = fmaxf(mx0, __shfl_xor_sync(0xffffffffu, mx0, 2));
            mx1 = fmaxf(mx1, __shfl_xor_sync(0xffffffffu, mx1, 1));
            mx1 = fmaxf(mx1, __shfl_xor_sync(0xffffffffu, mx1, 2));

            const float mn0 = fmaxf(m[mh][0], mx0);
            const float mn1 = fmaxf(m[mh][1], mx1);
            corr[mh][0] = ex2(m[mh][0] - mn0);
            corr[mh][1] = ex2(m[mh][1] - mn1);
            m[mh][0] = mn0; m[mh][1] = mn1;

            float ls0 = 0.f, ls1 = 0.f;
#pragma unroll
            for (int nt = 0; nt < 4; nt++) {
                sc[mh][nt][0] = ex2(sc[mh][nt][0] - mn0);
                sc[mh][nt][1] = ex2(sc[mh][nt][1] - mn0);
                sc[mh][nt][2] = ex2(sc[mh][nt][2] - mn1);
                sc[mh][nt][3] = ex2(sc[mh][nt][3] - mn1);
                ls0 += sc[mh][nt][0] + sc[mh][nt][1];
                ls1 += sc[mh][nt][2] + sc[mh][nt][3];
            }
            ls0 += __shfl_xor_sync(0xffffffffu, ls0, 1);
            ls0 += __shfl_xor_sync(0xffffffffu, ls0, 2);
            ls1 += __shfl_xor_sync(0xffffffffu, ls1, 1);
            ls1 += __shfl_xor_sync(0xffffffffu, ls1, 2);
            l[mh][0] = l[mh][0] * corr[mh][0] + ls0;
            l[mh][1] = l[mh][1] * corr[mh][1] + ls1;

#pragma unroll
            for (int nt = 0; nt < 8; nt++) {
                o[mh][nt][0] *= corr[mh][0]; o[mh][nt][1] *= corr[mh][0];
                o[mh][nt][2] *= corr[mh][1]; o[mh][nt][3] *= corr[mh][1];
            }
        }

        // ---- O += P V : shuffle P C-fragments into A-fragments ----
        const uint32_t* vbase = sV + t4 * VP + g4;
#pragma unroll
        for (int kk = 0; kk < 4; kk++) {
            uint32_t pa[2][4];
#pragma unroll
            for (int mh = 0; mh < 2; mh++) {
                const float v0 = __shfl_sync(0xffffffffu, sc[mh][kk][0], srcA);
                const float v1 = __shfl_sync(0xffffffffu, sc[mh][kk][1], srcA);
                const float v2 = __shfl_sync(0xffffffffu, sc[mh][kk][2], srcA);
                const float v3 = __shfl_sync(0xffffffffu, sc[mh][kk][3], srcA);
                const float v4 = __shfl_sync(0xffffffffu, sc[mh][kk][0], srcB);
                const float v5 = __shfl_sync(0xffffffffu, sc[mh][kk][1], srcB);
                const float v6 = __shfl_sync(0xffffffffu, sc[mh][kk][2], srcB);
                const float v7 = __shfl_sync(0xffffffffu, sc[mh][kk][3], srcB);
                pa[mh][0] = f2t(odd ? v1 : v0);
                pa[mh][1] = f2t(odd ? v3 : v2);
                pa[mh][2] = f2t(odd ? v5 : v4);
                pa[mh][3] = f2t(odd ? v7 : v6);
            }
            const uint32_t* vrow = vbase + kk * 8 * VP;
#pragma unroll
            for (int nt = 0; nt < 8; nt++) {
                const uint32_t b0 = vrow[nt * 8];
                const uint32_t b1 = vrow[4 * VP + nt * 8];
                mma8(o[0][nt], pa[0][0], pa[0][1], pa[0][2], pa[0][3], b0, b1);
                mma8(o[1][nt], pa[1][0], pa[1][1], pa[1][2], pa[1][3], b0, b1);
            }
        }

        __syncthreads();
        if (kb + 2 < nkb) { prefetch(kb & 1, kb + 2); cpa_commit(); }
    }

    // ---- epilogue: normalize, store tf32 bits to [s][d] ----
#pragma unroll
    for (int mh = 0; mh < 2; mh++) {
        const float inv0 = 1.f / l[mh][0];
        const float inv1 = 1.f / l[mh][1];
        const int r0 = qblk * 128 + wid * 32 + mh * 16 + g4;
#pragma unroll
        for (int nt = 0; nt < 8; nt++) {
            const int col = head * HDIM + nt * 8 + (t4 << 1);
            *(float2*)(att + (size_t)r0 * DIM + col) = make_float2(
                __uint_as_float(f2t(o[mh][nt][0] * inv0)),
                __uint_as_float(f2t(o[mh][nt][1] * inv0)));
            *(float2*)(att + (size_t)(r0 + 8) * DIM + col) = make_float2(
                __uint_as_float(f2t(o[mh][nt][2] * inv1)),
                __uint_as_float(f2t(o[mh][nt][3] * inv1)));
        }
    }
}

// ---------------------------------------------------------------------------
// Launch
// ---------------------------------------------------------------------------
extern "C" void kernel_launch(void* const* d_in, const int* in_sizes, int n_in,
                              void* d_out, int out_size)
{
    const float* x    = (const float*)d_in[0];
    const float* cosT = (const float*)d_in[1];
    const float* sinT = (const float*)d_in[2];
    const float* wq   = (const float*)d_in[4];
    const float* wk   = (const float*)d_in[5];
    const float* wv   = (const float*)d_in[6];
    const float* wo   = (const float*)d_in[7];
    float* out = (float*)d_out;

    float *qp, *kp, *vp, *ap, *xt, *wqt, *wkt, *wvt, *wot;
    cudaGetSymbolAddress((void**)&qp, g_q);
    cudaGetSymbolAddress((void**)&kp, g_k);
    cudaGetSymbolAddress((void**)&vp, g_v);
    cudaGetSymbolAddress((void**)&ap, g_att);
    cudaGetSymbolAddress((void**)&xt, g_xt);
    cudaGetSymbolAddress((void**)&wqt, g_wq);
    cudaGetSymbolAddress((void**)&wkt, g_wk);
    cudaGetSymbolAddress((void**)&wvt, g_wv);
    cudaGetSymbolAddress((void**)&wot, g_wo);

    cudaFuncSetAttribute(flash_reg,
                         cudaFuncAttributeMaxDynamicSharedMemorySize, FLASH_SMEM);
    cudaFuncSetAttribute(gemm_tf32,
                         cudaFuncAttributeMaxDynamicSharedMemorySize, GSMEM);

    // Convert inputs to tf32 bits once
    cvt_tf32<<<512, 256>>>(x, xt, SEQ * DIM / 4);
    dim3 wgrid(128, 1, 4);
    cvt_tf32_w<<<wgrid, 256>>>(wq, wqt, wk, wkt, wv, wvt, wo, wot, DIM * DIM / 4);

    // Fused QKV projections (z = 0,1,2 -> Q,K,V)
    dim3 ggrid(DIM / 128, SEQ / 128, 3);
    gemm_tf32<<<ggrid, 256, GSMEM>>>(xt, wqt, wkt, wvt, qp, kp, vp, cosT, sinT, 1);

    dim3 fgrid(SEQ / 128, NH);
    flash_reg<<<fgrid, 128, FLASH_SMEM>>>(qp, kp, vp, ap);

    // Output projection
    dim3 ogrid(DIM / 128, SEQ / 128, 1);
    gemm_tf32<<<ogrid, 256, GSMEM>>>(ap, wot, wot, wot, out, out, out, cosT, sinT, 0);
}

// round 10
// speedup vs baseline: 5.2137x; 1.0298x over previous
#include <cuda_runtime.h>
#include <math.h>
#include <stdint.h>

#define SEQ 4096
#define DIM 1024
#define NH  16
#define HDIM 64

// Scratch (tf32 bits stored as float)
__device__ float g_q[NH * SEQ * HDIM];   // [h][s][hd] tf32, pre-scaled
__device__ float g_k[NH * SEQ * HDIM];   // [h][s][hd] tf32
__device__ float g_v[NH * SEQ * HDIM];   // [h][s][hd] tf32
__device__ float g_att[SEQ * DIM];       // [s][d]     tf32
__device__ float g_xt[SEQ * DIM];        // x as tf32
__device__ float g_wq[DIM * DIM];        // weights as tf32
__device__ float g_wk[DIM * DIM];
__device__ float g_wv[DIM * DIM];
__device__ float g_wo[DIM * DIM];

#define QSCALE (0.125f * 1.4426950408889634f)   // 1/sqrt(64) * log2(e)

__device__ __forceinline__ uint32_t f2t(float f) {
    uint32_t u;
    asm("cvt.rna.tf32.f32 %0, %1;" : "=r"(u) : "f"(f));
    return u;
}

__device__ __forceinline__ float ex2(float x) {
    float r;
    asm("ex2.approx.f32 %0, %1;" : "=f"(r) : "f"(x));
    return r;
}

__device__ __forceinline__ void mma8(float c[4],
    uint32_t a0, uint32_t a1, uint32_t a2, uint32_t a3,
    uint32_t b0, uint32_t b1)
{
    asm volatile(
        "mma.sync.aligned.m16n8k8.row.col.f32.tf32.tf32.f32 "
        "{%0,%1,%2,%3},{%4,%5,%6,%7},{%8,%9},{%0,%1,%2,%3};"
        : "+f"(c[0]), "+f"(c[1]), "+f"(c[2]), "+f"(c[3])
        : "r"(a0), "r"(a1), "r"(a2), "r"(a3), "r"(b0), "r"(b1));
}

__device__ __forceinline__ void cpa16(uint32_t dst_smem, const void* src) {
    asm volatile("cp.async.cg.shared.global [%0], [%1], 16;"
                 :: "r"(dst_smem), "l"(src));
}
__device__ __forceinline__ void cpa_commit() {
    asm volatile("cp.async.commit_group;");
}
template<int N>
__device__ __forceinline__ void cpa_wait() {
    asm volatile("cp.async.wait_group %0;" :: "n"(N));
}

// ---------------------------------------------------------------------------
// Convert fp32 -> tf32 bits
// ---------------------------------------------------------------------------
__global__ void cvt_tf32(const float* __restrict__ src, float* __restrict__ dst,
                         int n4)
{
    for (int i = blockIdx.x * blockDim.x + threadIdx.x; i < n4;
         i += gridDim.x * blockDim.x) {
        float4 v = ((const float4*)src)[i];
        v.x = __uint_as_float(f2t(v.x));
        v.y = __uint_as_float(f2t(v.y));
        v.z = __uint_as_float(f2t(v.z));
        v.w = __uint_as_float(f2t(v.w));
        ((float4*)dst)[i] = v;
    }
}

__global__ void cvt_tf32_w(const float* __restrict__ s0, float* __restrict__ d0,
                           const float* __restrict__ s1, float* __restrict__ d1,
                           const float* __restrict__ s2, float* __restrict__ d2,
                           const float* __restrict__ s3, float* __restrict__ d3,
                           int n4)
{
    const float* src; float* dst;
    if (blockIdx.z == 0)      { src = s0; dst = d0; }
    else if (blockIdx.z == 1) { src = s1; dst = d1; }
    else if (blockIdx.z == 2) { src = s2; dst = d2; }
    else                      { src = s3; dst = d3; }
    for (int i = blockIdx.x * blockDim.x + threadIdx.x; i < n4;
         i += gridDim.x * blockDim.x) {
        float4 v = ((const float4*)src)[i];
        v.x = __uint_as_float(f2t(v.x));
        v.y = __uint_as_float(f2t(v.y));
        v.z = __uint_as_float(f2t(v.z));
        v.w = __uint_as_float(f2t(v.w));
        ((float4*)dst)[i] = v;
    }
}

// ---------------------------------------------------------------------------
// TF32 GEMM (mma.sync), 64x64 warp tiles, 128 threads (2x2 warps),
// BK=32, 3-stage cp.async, ONE barrier per chunk.
// C[4096,1024] = A[M,K] * W[N,K]^T ; 128x128 CTA tile.
// mode 0: plain f32 out; 1: RoPE+QSCALE->tf32 [h][s][hd];
// 2: RoPE->tf32 [h][s][hd]; 3: tf32 [h][s][hd]
// ---------------------------------------------------------------------------
#define GBK   32
#define GSAS  36
#define GSTW  (128 * GSAS)
#define GSTB  (2 * GSTW * 4)
#define GSMEM (3 * GSTB)

__global__ void __launch_bounds__(128) gemm_tf32(
    const float* __restrict__ A,
    const float* __restrict__ W0, const float* __restrict__ W1,
    const float* __restrict__ W2,
    float* __restrict__ out0, float* __restrict__ out1,
    float* __restrict__ out2,
    const float* __restrict__ cosT, const float* __restrict__ sinT,
    int mode0)
{
    extern __shared__ uint32_t gsm[];

    const float* W; float* out; int mode;
    if (blockIdx.z == 0)      { W = W0; out = out0; mode = mode0; }
    else if (blockIdx.z == 1) { W = W1; out = out1; mode = 2; }
    else                      { W = W2; out = out2; mode = 3; }

    const int tid  = threadIdx.x;
    const int lane = tid & 31;
    const int wid  = tid >> 5;
    const int wm   = wid >> 1;      // 0..1
    const int wn   = wid & 1;       // 0..1
    const int g4   = lane >> 2;
    const int t4   = lane & 3;

    const int mBase = blockIdx.y * 128;
    const int nBase = blockIdx.x * 128;

    const uint32_t smemu = (uint32_t)__cvta_generic_to_shared(gsm);

    auto prefetch = [&](int s, int t) {
        const int koff = t * GBK;
        const uint32_t abase = smemu + s * GSTB;
        const uint32_t bbase = abase + GSTW * 4;
#pragma unroll
        for (int j = 0; j < 8; j++) {
            const int idx = tid + j * 128;       // 0..1023
            const int r = idx >> 3, c4 = (idx & 7) << 2;
            cpa16(abase + (r * GSAS + c4) * 4, A + (size_t)(mBase + r) * DIM + koff + c4);
            cpa16(bbase + (r * GSAS + c4) * 4, W + (size_t)(nBase + r) * DIM + koff + c4);
        }
    };

    float c[4][8][4];
#pragma unroll
    for (int mt = 0; mt < 4; mt++)
#pragma unroll
        for (int nt = 0; nt < 8; nt++)
#pragma unroll
            for (int i = 0; i < 4; i++) c[mt][nt][i] = 0.f;

    const int NT = DIM / GBK;
    prefetch(0, 0); cpa_commit();
    prefetch(1, 1); cpa_commit();

    for (int t = 0; t < NT; t++) {
        if (t + 1 < NT) cpa_wait<1>(); else cpa_wait<0>();
        __syncthreads();

        if (t + 2 < NT) { prefetch((t + 2) % 3, t + 2); cpa_commit(); }

        const uint32_t* a_s = gsm + (t % 3) * (GSTB / 4);
        const uint32_t* b_s = a_s + GSTW;
#pragma unroll
        for (int ks = 0; ks < 4; ks++) {
            const int kk = ks * 8 + t4;
            uint32_t af[4][4], bf[8][2];
#pragma unroll
            for (int mt = 0; mt < 4; mt++) {
                const int r = wm * 64 + mt * 16 + g4;
                af[mt][0] = a_s[r * GSAS + kk];
                af[mt][1] = a_s[(r + 8) * GSAS + kk];
                af[mt][2] = a_s[r * GSAS + kk + 4];
                af[mt][3] = a_s[(r + 8) * GSAS + kk + 4];
            }
#pragma unroll
            for (int nt = 0; nt < 8; nt++) {
                const int r = wn * 64 + nt * 8 + g4;
                bf[nt][0] = b_s[r * GSAS + kk];
                bf[nt][1] = b_s[r * GSAS + kk + 4];
            }
#pragma unroll
            for (int mt = 0; mt < 4; mt++)
#pragma unroll
                for (int nt = 0; nt < 8; nt++)
                    mma8(c[mt][nt], af[mt][0], af[mt][1], af[mt][2], af[mt][3],
                         bf[nt][0], bf[nt][1]);
        }
    }

#pragma unroll
    for (int mt = 0; mt < 4; mt++) {
        const int r0 = mBase + wm * 64 + mt * 16 + g4;
#pragma unroll
        for (int nt = 0; nt < 8; nt++) {
            const int colg = nBase + wn * 64 + nt * 8 + (t4 << 1);
            const float* cc = c[mt][nt];
            if (mode == 0) {
                *(float2*)(out + (size_t)r0 * DIM + colg)       = make_float2(cc[0], cc[1]);
                *(float2*)(out + (size_t)(r0 + 8) * DIM + colg) = make_float2(cc[2], cc[3]);
            } else {
                const int head = colg >> 6;
                const int hd   = colg & 63;
                const int f    = hd >> 1;
#pragma unroll
                for (int h = 0; h < 2; h++) {
                    const int row = r0 + h * 8;
                    float e = cc[h * 2 + 0], o = cc[h * 2 + 1];
                    float re = e, ro = o;
                    if (mode != 3) {
                        const float cth = cosT[row * 32 + f];
                        const float sth = sinT[row * 32 + f];
                        re = e * cth - o * sth;
                        ro = e * sth + o * cth;
                        if (mode == 1) { re *= QSCALE; ro *= QSCALE; }
                    }
                    float* dst = out + ((size_t)head * SEQ + row) * HDIM + hd;
                    dst[0] = __uint_as_float(f2t(re));
                    dst[1] = __uint_as_float(f2t(ro));
                }
            }
        }
    }
}

// ---------------------------------------------------------------------------
// TF32 flash attention, M=32 warp tile, 32-key tiles.
// Q repacked ONCE into fragment-major smem (8192 words — FIXED from R9):
// each (wid,kk,mh,g4,t4) A-fragment is one aligned 16B chunk -> LDS.128.
// CTA = 128 threads, 128 queries.
// smem: sQf[8192 words] + 2 stages of (K[32][68] + V[32][72]).
// ---------------------------------------------------------------------------
#define FP  68
#define VP  72
#define KT  32
#define SQF_W  8192                          // fragment-major Q words (128x64)
#define STAGE_W (KT * FP + KT * VP)          // 4480 words
#define FLASH_SMEM ((SQF_W + 2 * STAGE_W) * (int)sizeof(uint32_t))   // 68608 B

__global__ void __launch_bounds__(128, 3) flash_reg(
    const float* __restrict__ Q, const float* __restrict__ K,
    const float* __restrict__ V, float* __restrict__ att)
{
    extern __shared__ uint32_t fsm[];
    uint32_t* sQf = fsm;

    const int tid  = threadIdx.x;
    const int lane = tid & 31;
    const int wid  = tid >> 5;
    const int g4   = lane >> 2;
    const int t4   = lane & 3;

    const int qblk = gridDim.x - 1 - blockIdx.x;   // longest first
    const int head = blockIdx.y;

    const uint32_t smemu = (uint32_t)__cvta_generic_to_shared(fsm);
    const float* Kh0 = K + (size_t)head * SEQ * HDIM;
    const float* Vh0 = V + (size_t)head * SEQ * HDIM;

    // prefetch one 32-key tile (K + V) into stage buf
    auto prefetch = [&](int buf, int kb) {
        const uint32_t base = smemu + (SQF_W + buf * STAGE_W) * 4;
        const float* Kh = Kh0 + (size_t)kb * KT * HDIM;
        const float* Vh = Vh0 + (size_t)kb * KT * HDIM;
#pragma unroll
        for (int j = 0; j < 4; j++) {
            const int idx = tid + j * 128;       // 0..511
            const int r = idx >> 4, c4 = (idx & 15) << 2;
            cpa16(base + (r * FP + c4) * 4, Kh + r * HDIM + c4);
            cpa16(base + (KT * FP + r * VP + c4) * 4, Vh + r * HDIM + c4);
        }
    };

    const int nkb = 4 * qblk + 4;   // 32-key tiles
    prefetch(0, 0); cpa_commit();
    prefetch(1, 1); cpa_commit();

    // ---- repack Q (128 x 64) into fragment-major layout (one time) ----
    // word addr = ((wid*8+kk)*2+mh)*128 + g4*16 + t4*4 + s
    //   s = rowH + 2*colH; r = wid*32+mh*16+rowH*8+g4; c = kk*8+colH*4+t4
    {
        const float* Qh = Q + ((size_t)head * SEQ + qblk * 128) * HDIM;
#pragma unroll
        for (int j = 0; j < 16; j++) {
            const int idx = tid + j * 128;       // 0..2047
            const int r = idx >> 4, c4 = (idx & 15) << 2;
            float4 v = *(const float4*)(Qh + (size_t)r * HDIM + c4);
            const int widr = r >> 5, mh = (r >> 4) & 1, g4r = r & 7;
            const int rowH = (r >> 3) & 1;
            const int kk = c4 >> 3, colH = (c4 >> 2) & 1;
            const int s = rowH + 2 * colH;
            uint32_t* dst = sQf + (((widr * 8 + kk) * 2 + mh) * 8 + g4r) * 16 + s;
            dst[0]  = __float_as_uint(v.x);
            dst[4]  = __float_as_uint(v.y);
            dst[8]  = __float_as_uint(v.z);
            dst[12] = __float_as_uint(v.w);
        }
    }

    float o[2][8][4];
#pragma unroll
    for (int mh = 0; mh < 2; mh++)
#pragma unroll
        for (int nt = 0; nt < 8; nt++)
#pragma unroll
            for (int i = 0; i < 4; i++) o[mh][nt][i] = 0.f;

    float m[2][2], l[2][2];
#pragma unroll
    for (int mh = 0; mh < 2; mh++) {
        m[mh][0] = -INFINITY; m[mh][1] = -INFINITY;
        l[mh][0] = 0.f;       l[mh][1] = 0.f;
    }

    const int srcA = (lane & 28) | (t4 >> 1);
    const int srcB = srcA + 2;
    const bool odd = (t4 & 1);

    __syncthreads();   // Q repack visible to all warps

    const uint32_t* qbase = sQf + wid * 2048 + g4 * 16 + t4 * 4;

    for (int kb = 0; kb < nkb; kb++) {
        if (kb + 1 < nkb) cpa_wait<1>(); else cpa_wait<0>();
        __syncthreads();

        const uint32_t* sK = fsm + SQF_W + (kb & 1) * STAGE_W;
        const uint32_t* sV = sK + KT * FP;

        // ---- S = Q K^T (Q fragments: one LDS.128 per (kk, mh)) ----
        float sc[2][4][4];
#pragma unroll
        for (int mh = 0; mh < 2; mh++)
#pragma unroll
            for (int nt = 0; nt < 4; nt++)
#pragma unroll
                for (int i = 0; i < 4; i++) sc[mh][nt][i] = 0.f;

        const uint32_t* kbase = sK + g4 * FP + t4;
#pragma unroll
        for (int kk = 0; kk < 8; kk++) {
            const uint4 qa0 = *(const uint4*)(qbase + kk * 256);
            const uint4 qa1 = *(const uint4*)(qbase + kk * 256 + 128);
#pragma unroll
            for (int nt = 0; nt < 4; nt++) {
                const uint32_t* bp = kbase + nt * 8 * FP + kk * 8;
                const uint32_t b0 = bp[0], b1 = bp[4];
                mma8(sc[0][nt], qa0.x, qa0.y, qa0.z, qa0.w, b0, b1);
                mma8(sc[1][nt], qa1.x, qa1.y, qa1.z, qa1.w, b0, b1);
            }
        }

        // ---- causal mask (diagonal tiles only) ----
        if (kb >= 4 * qblk) {
#pragma unroll
            for (int mh = 0; mh < 2; mh++) {
                const int r0 = qblk * 128 + wid * 32 + mh * 16 + g4;
                const int r1 = r0 + 8;
#pragma unroll
                for (int nt = 0; nt < 4; nt++) {
                    const int col = kb * KT + nt * 8 + (t4 << 1);
                    if (col > r0)     sc[mh][nt][0] = -INFINITY;
                    if (col + 1 > r0) sc[mh][nt][1] = -INFINITY;
                    if (col > r1)     sc[mh][nt][2] = -INFINITY;
                    if (col + 1 > r1) sc[mh][nt][3] = -INFINITY;
                }
            }
        }

        // ---- online softmax (log2 domain) ----
        float corr[2][2];
#pragma unroll
        for (int mh = 0; mh < 2; mh++) {
            float mx0 = -INFINITY, mx1 = -INFINITY;
#pragma unroll
            for (int nt = 0; nt < 4; nt++) {
                mx0 = fmaxf(mx0, fmaxf(sc[mh][nt][0], sc[mh][nt][1]));
                mx1 = fmaxf(mx1, fmaxf(sc[mh][nt][2], sc[mh][nt][3]));
            }
            mx0 = fmaxf(mx0, __shfl_xor_sync(0xffffffffu, mx0, 1));
            mx0 = fmaxf(mx0, __shfl_xor_sync(0xffffffffu, mx0, 2));
            mx1 = fmaxf(mx1, __shfl_xor_sync(0xffffffffu, mx1, 1));
            mx1 = fmaxf(mx1, __shfl_xor_sync(0xffffffffu, mx1, 2));

            const float mn0 = fmaxf(m[mh][0], mx0);
            const float mn1 = fmaxf(m[mh][1], mx1);
            corr[mh][0] = ex2(m[mh][0] - mn0);
            corr[mh][1] = ex2(m[mh][1] - mn1);
            m[mh][0] = mn0; m[mh][1] = mn1;

            float ls0 = 0.f, ls1 = 0.f;
#pragma unroll
            for (int nt = 0; nt < 4; nt++) {
                sc[mh][nt][0] = ex2(sc[mh][nt][0] - mn0);
                sc[mh][nt][1] = ex2(sc[mh][nt][1] - mn0);
                sc[mh][nt][2] = ex2(sc[mh][nt][2] - mn1);
                sc[mh][nt][3] = ex2(sc[mh][nt][3] - mn1);
                ls0 += sc[mh][nt][0] + sc[mh][nt][1];
                ls1 += sc[mh][nt][2] + sc[mh][nt][3];
            }
            ls0 += __shfl_xor_sync(0xffffffffu, ls0, 1);
            ls0 += __shfl_xor_sync(0xffffffffu, ls0, 2);
            ls1 += __shfl_xor_sync(0xffffffffu, ls1, 1);
            ls1 += __shfl_xor_sync(0xffffffffu, ls1, 2);
            l[mh][0] = l[mh][0] * corr[mh][0] + ls0;
            l[mh][1] = l[mh][1] * corr[mh][1] + ls1;

#pragma unroll
            for (int nt = 0; nt < 8; nt++) {
                o[mh][nt][0] *= corr[mh][0]; o[mh][nt][1] *= corr[mh][0];
                o[mh][nt][2] *= corr[mh][1]; o[mh][nt][3] *= corr[mh][1];
            }
        }

        // ---- O += P V : shuffle P C-fragments into A-fragments ----
        const uint32_t* vbase = sV + t4 * VP + g4;
#pragma unroll
        for (int kk = 0; kk < 4; kk++) {
            uint32_t pa[2][4];
#pragma unroll
            for (int mh = 0; mh < 2; mh++) {
                const float v0 = __shfl_sync(0xffffffffu, sc[mh][kk][0], srcA);
                const float v1 = __shfl_sync(0xffffffffu, sc[mh][kk][1], srcA);
                const float v2 = __shfl_sync(0xffffffffu, sc[mh][kk][2], srcA);
                const float v3 = __shfl_sync(0xffffffffu, sc[mh][kk][3], srcA);
                const float v4 = __shfl_sync(0xffffffffu, sc[mh][kk][0], srcB);
                const float v5 = __shfl_sync(0xffffffffu, sc[mh][kk][1], srcB);
                const float v6 = __shfl_sync(0xffffffffu, sc[mh][kk][2], srcB);
                const float v7 = __shfl_sync(0xffffffffu, sc[mh][kk][3], srcB);
                pa[mh][0] = f2t(odd ? v1 : v0);
                pa[mh][1] = f2t(odd ? v3 : v2);
                pa[mh][2] = f2t(odd ? v5 : v4);
                pa[mh][3] = f2t(odd ? v7 : v6);
            }
            const uint32_t* vrow = vbase + kk * 8 * VP;
#pragma unroll
            for (int nt = 0; nt < 8; nt++) {
                const uint32_t b0 = vrow[nt * 8];
                const uint32_t b1 = vrow[4 * VP + nt * 8];
                mma8(o[0][nt], pa[0][0], pa[0][1], pa[0][2], pa[0][3], b0, b1);
                mma8(o[1][nt], pa[1][0], pa[1][1], pa[1][2], pa[1][3], b0, b1);
            }
        }

        __syncthreads();
        if (kb + 2 < nkb) { prefetch(kb & 1, kb + 2); cpa_commit(); }
    }

    // ---- epilogue: normalize, store tf32 bits to [s][d] ----
#pragma unroll
    for (int mh = 0; mh < 2; mh++) {
        const float inv0 = 1.f / l[mh][0];
        const float inv1 = 1.f / l[mh][1];
        const int r0 = qblk * 128 + wid * 32 + mh * 16 + g4;
#pragma unroll
        for (int nt = 0; nt < 8; nt++) {
            const int col = head * HDIM + nt * 8 + (t4 << 1);
            *(float2*)(att + (size_t)r0 * DIM + col) = make_float2(
                __uint_as_float(f2t(o[mh][nt][0] * inv0)),
                __uint_as_float(f2t(o[mh][nt][1] * inv0)));
            *(float2*)(att + (size_t)(r0 + 8) * DIM + col) = make_float2(
                __uint_as_float(f2t(o[mh][nt][2] * inv1)),
                __uint_as_float(f2t(o[mh][nt][3] * inv1)));
        }
    }
}

// ---------------------------------------------------------------------------
// Launch
// ---------------------------------------------------------------------------
extern "C" void kernel_launch(void* const* d_in, const int* in_sizes, int n_in,
                              void* d_out, int out_size)
{
    const float* x    = (const float*)d_in[0];
    const float* cosT = (const float*)d_in[1];
    const float* sinT = (const float*)d_in[2];
    const float* wq   = (const float*)d_in[4];
    const float* wk   = (const float*)d_in[5];
    const float* wv   = (const float*)d_in[6];
    const float* wo   = (const float*)d_in[7];
    float* out = (float*)d_out;

    float *qp, *kp, *vp, *ap, *xt, *wqt, *wkt, *wvt, *wot;
    cudaGetSymbolAddress((void**)&qp, g_q);
    cudaGetSymbolAddress((void**)&kp, g_k);
    cudaGetSymbolAddress((void**)&vp, g_v);
    cudaGetSymbolAddress((void**)&ap, g_att);
    cudaGetSymbolAddress((void**)&xt, g_xt);
    cudaGetSymbolAddress((void**)&wqt, g_wq);
    cudaGetSymbolAddress((void**)&wkt, g_wk);
    cudaGetSymbolAddress((void**)&wvt, g_wv);
    cudaGetSymbolAddress((void**)&wot, g_wo);

    cudaFuncSetAttribute(flash_reg,
                         cudaFuncAttributeMaxDynamicSharedMemorySize, FLASH_SMEM);
    cudaFuncSetAttribute(gemm_tf32,
                         cudaFuncAttributeMaxDynamicSharedMemorySize, GSMEM);

    // Convert inputs to tf32 bits once
    cvt_tf32<<<512, 256>>>(x, xt, SEQ * DIM / 4);
    dim3 wgrid(128, 1, 4);
    cvt_tf32_w<<<wgrid, 256>>>(wq, wqt, wk, wkt, wv, wvt, wo, wot, DIM * DIM / 4);

    // Fused QKV projections (z = 0,1,2 -> Q,K,V)
    dim3 ggrid(DIM / 128, SEQ / 128, 3);
    gemm_tf32<<<ggrid, 128, GSMEM>>>(xt, wqt, wkt, wvt, qp, kp, vp, cosT, sinT, 1);

    dim3 fgrid(SEQ / 128, NH);
    flash_reg<<<fgrid, 128, FLASH_SMEM>>>(qp, kp, vp, ap);

    // Output projection
    dim3 ogrid(DIM / 128, SEQ / 128, 1);
    gemm_tf32<<<ogrid, 128, GSMEM>>>(ap, wot, wot, wot, out, out, out, cosT, sinT, 0);
}